// round 13
// baseline (speedup 1.0000x reference)
#include <cuda_runtime.h>
#include <cuda_bf16.h>
#include <cstdint>

#define B_   4
#define C_   128
#define H_   64
#define W_   64
#define KS_  7
#define PAD_ 3
#define NC_  8      // channel chunks
#define CC_  16     // channels per chunk ( == O/GROUPS )
#define HW_  (H_*W_)

#define CHUNK_STRIDE_ ((size_t)H_*W_*CC_)            // per (b,cc) plane
#define MAT_STRIDE_   ((size_t)B_*NC_*H_*W_*CC_)     // per q/k/v matrix

// Scratch for q,k,v in chunked pixel-major layout: [mat][b][cc][y][x][16]
__device__ __align__(16) float g_qkv[3ull * B_ * NC_ * H_ * W_ * CC_];

// ---------------- Kernel 1: QKV projection via mma.sync bf16-split -----------
#define WLDH_ 136
#define PALD_ 72                               // A pitch in halfs (144 B rows)
#define PSA_HI_ 0
#define PSA_LO_ (PSA_HI_ + 128 * PALD_ * 2)    // 18432
#define PSW_HI_ (PSA_LO_ + 128 * PALD_ * 2)    // 36864
#define PSW_LO_ (PSW_HI_ + 128 * WLDH_ * 2)    // 71680
#define PSM_BYTES_ (PSW_LO_ + 128 * WLDH_ * 2) // 106496  -> 2 CTAs/SM

__device__ __forceinline__ uint32_t smem_u32(const void* p) {
    uint32_t a;
    asm("{ .reg .u64 t; cvta.to.shared.u64 t, %1; cvt.u32.u64 %0, t; }"
        : "=r"(a) : "l"(p));
    return a;
}
__device__ __forceinline__ void ldsm_x4_trans(uint32_t* r, uint32_t addr) {
    asm volatile("ldmatrix.sync.aligned.m8n8.x4.trans.shared.b16 {%0,%1,%2,%3}, [%4];"
                 : "=r"(r[0]), "=r"(r[1]), "=r"(r[2]), "=r"(r[3]) : "r"(addr));
}
__device__ __forceinline__ void ldsm_x2(uint32_t& b0, uint32_t& b1, uint32_t addr) {
    asm volatile("ldmatrix.sync.aligned.m8n8.x2.shared.b16 {%0,%1}, [%2];"
                 : "=r"(b0), "=r"(b1) : "r"(addr));
}
__device__ __forceinline__ void mma16816(float* d, const uint32_t* a,
                                         uint32_t b0, uint32_t b1) {
    asm volatile(
        "mma.sync.aligned.m16n8k16.row.col.f32.bf16.bf16.f32 "
        "{%0,%1,%2,%3}, {%4,%5,%6,%7}, {%8,%9}, {%0,%1,%2,%3};"
        : "+f"(d[0]), "+f"(d[1]), "+f"(d[2]), "+f"(d[3])
        : "r"(a[0]), "r"(a[1]), "r"(a[2]), "r"(a[3]), "r"(b0), "r"(b1));
}
__device__ __forceinline__ void split4(float4 v, uint2& hi, uint2& lo) {
    float vv[4] = {v.x, v.y, v.z, v.w};
    unsigned short h[4], l[4];
#pragma unroll
    for (int e = 0; e < 4; e++) {
        __nv_bfloat16 hb = __float2bfloat16(vv[e]);
        __nv_bfloat16 lb = __float2bfloat16(vv[e] - __bfloat162float(hb));
        h[e] = __bfloat16_as_ushort(hb);
        l[e] = __bfloat16_as_ushort(lb);
    }
    hi = make_uint2((uint32_t)h[0] | ((uint32_t)h[1] << 16),
                    (uint32_t)h[2] | ((uint32_t)h[3] << 16));
    lo = make_uint2((uint32_t)l[0] | ((uint32_t)l[1] << 16),
                    (uint32_t)l[2] | ((uint32_t)l[3] << 16));
}

__global__ void __launch_bounds__(256, 2) proj_mma_kernel(
    const float* __restrict__ x, const float* __restrict__ wq,
    const float* __restrict__ wk, const float* __restrict__ wv)
{
    extern __shared__ char sm[];
    const uint32_t smb = smem_u32(sm);
    const int t = threadIdx.x;
    const int pxbase = blockIdx.x * 64;
    const int b = blockIdx.y;

#pragma unroll
    for (int j = 0; j < 8; j++) {
        int idx = t + j * 256;
        int c  = idx >> 4;
        int p4 = idx & 15;
        float4 v = *(const float4*)(x + ((size_t)(b * C_ + c)) * HW_ + pxbase + p4 * 4);
        uint2 hi, lo; split4(v, hi, lo);
        uint32_t off = (uint32_t)(c * PALD_ + p4 * 4) * 2;
        *(uint2*)(sm + PSA_HI_ + off) = hi;
        *(uint2*)(sm + PSA_LO_ + off) = lo;
    }

    const int w = t >> 5, lane = t & 31;
    const int m0 = (w & 1) * 32;
    const int n0 = (w >> 1) * 32;
    const int lq = lane & 15;

    const uint32_t a_base = smb + PSA_HI_ +
        (uint32_t)(((lane & 7) + ((lane >> 4) & 1) * 8) * PALD_ +
                   (m0 + ((lane >> 3) & 1) * 8)) * 2;
    const uint32_t b_base = smb + PSW_HI_ +
        (uint32_t)((n0 + (lq & 7)) * WLDH_) * 2 + ((lq >> 3) & 1) * 16;

#pragma unroll 1
    for (int mat = 0; mat < 3; mat++) {
        const float* wsrc = (mat == 0) ? wq : (mat == 1) ? wk : wv;

#pragma unroll
        for (int j = 0; j < 16; j++) {
            int idx = t + j * 256;
            int n  = idx >> 5;
            int k4 = idx & 31;
            float4 v = *(const float4*)(wsrc + n * 128 + k4 * 4);
            uint2 hi, lo; split4(v, hi, lo);
            uint32_t off = (uint32_t)(n * WLDH_ + k4 * 4) * 2;
            *(uint2*)(sm + PSW_HI_ + off) = hi;
            *(uint2*)(sm + PSW_LO_ + off) = lo;
        }
        __syncthreads();

        float acc[2][4][4];
#pragma unroll
        for (int mt = 0; mt < 2; mt++)
#pragma unroll
            for (int nt = 0; nt < 4; nt++)
#pragma unroll
                for (int e = 0; e < 4; e++) acc[mt][nt][e] = 0.f;

#pragma unroll
        for (int ks = 0; ks < 8; ks++) {
            uint32_t ahi[2][4], alo[2][4];
#pragma unroll
            for (int mt = 0; mt < 2; mt++) {
                uint32_t aa = a_base + (uint32_t)(ks * 16 * PALD_ * 2 + mt * 32);
                ldsm_x4_trans(ahi[mt], aa);
                ldsm_x4_trans(alo[mt], aa + (PSA_LO_ - PSA_HI_));
            }
#pragma unroll
            for (int nt = 0; nt < 4; nt++) {
                uint32_t ba = b_base + (uint32_t)(nt * 8 * WLDH_ * 2 + ks * 32);
                uint32_t bh0, bh1, bl0, bl1;
                ldsm_x2(bh0, bh1, ba);
                ldsm_x2(bl0, bl1, ba + (PSW_LO_ - PSW_HI_));
#pragma unroll
                for (int mt = 0; mt < 2; mt++) {
                    mma16816(acc[mt][nt], ahi[mt], bh0, bh1);
                    mma16816(acc[mt][nt], ahi[mt], bl0, bl1);
                    mma16816(acc[mt][nt], alo[mt], bh0, bh1);
                }
            }
        }

#pragma unroll
        for (int mt = 0; mt < 2; mt++) {
#pragma unroll
            for (int nt = 0; nt < 4; nt++) {
                int nn = n0 + nt * 8 + (lane & 3) * 2;
                int cc = nn >> 4, ch16 = nn & 15;
                int flat = pxbase + m0 + mt * 16 + (lane >> 2);
                float* dst = g_qkv + (size_t)mat * MAT_STRIDE_ +
                             (size_t)(b * NC_ + cc) * CHUNK_STRIDE_ +
                             (size_t)flat * 16 + ch16;
                *(float2*)dst          = make_float2(acc[mt][nt][0], acc[mt][nt][1]);
                *(float2*)(dst + 128)  = make_float2(acc[mt][nt][2], acc[mt][nt][3]);
            }
        }
        __syncthreads();
    }
}

// ---------------- Kernel 2: windowed attention, 2 horizontal px / thread -----
// 16x8 tiles, 128 blocks, 256 threads = 4 groups x 64; group owns 2 chunks.
#define TW_ 16
#define TH_ 8
#define KW_ (TW_ + KS_ - 1)        // 22
#define KH_ (TH_ + KS_ - 1)        // 14
#define NGR_ 4
#define GT_  64                     // threads per group
#define PLANE_ (KH_ * KW_)          // 308
#define TILE_F4_ (4 * PLANE_)       // 1232
#define RED_STRIDE_ 65
#define SMEM_TILES_F4_ (NGR_ * 2 * TILE_F4_)
#define SMEM_BYTES_ (SMEM_TILES_F4_ * 16 + 128 * RED_STRIDE_ * 4 + 112 * 4)

__device__ __forceinline__ void cp_stage64(float4* __restrict__ dst,
                                           const float* __restrict__ base,
                                           int y0, int x0, int pid)
{
#pragma unroll
    for (int it = 0; it < 20; it++) {
        int i = pid + it * GT_;
        if (i < TILE_F4_) {
            int c4  = i / PLANE_;
            int rem = i - c4 * PLANE_;
            int yy  = rem / KW_;
            int xx  = rem - yy * KW_;
            int gy = y0 - PAD_ + yy, gx = x0 - PAD_ + xx;
            bool inb = ((unsigned)gy < H_) && ((unsigned)gx < W_);
            const float* src = base + ((size_t)(inb ? gy : 0) * W_ + (inb ? gx : 0)) * CC_ + c4 * 4;
            unsigned daddr = (unsigned)__cvta_generic_to_shared(dst + i);
            int sz = inb ? 16 : 0;
            asm volatile("cp.async.cg.shared.global [%0], [%1], 16, %2;"
                         :: "r"(daddr), "l"(src), "r"(sz));
        }
    }
}
__device__ __forceinline__ void cp_commit() {
    asm volatile("cp.async.commit_group;" ::: "memory");
}
__device__ __forceinline__ void cp_wait_all() {
    asm volatile("cp.async.wait_all;" ::: "memory");
}
__device__ __forceinline__ void group_bar(int g) {
    asm volatile("bar.sync %0, %1;" :: "r"(1 + g), "r"(GT_) : "memory");
}
__device__ __forceinline__ float dot16(const float4* q, float4 k0, float4 k1,
                                       float4 k2, float4 k3, float s) {
    s = fmaf(q[0].x, k0.x, s); s = fmaf(q[0].y, k0.y, s);
    s = fmaf(q[0].z, k0.z, s); s = fmaf(q[0].w, k0.w, s);
    s = fmaf(q[1].x, k1.x, s); s = fmaf(q[1].y, k1.y, s);
    s = fmaf(q[1].z, k1.z, s); s = fmaf(q[1].w, k1.w, s);
    s = fmaf(q[2].x, k2.x, s); s = fmaf(q[2].y, k2.y, s);
    s = fmaf(q[2].z, k2.z, s); s = fmaf(q[2].w, k2.w, s);
    s = fmaf(q[3].x, k3.x, s); s = fmaf(q[3].y, k3.y, s);
    s = fmaf(q[3].z, k3.z, s); s = fmaf(q[3].w, k3.w, s);
    return s;
}

__global__ void __launch_bounds__(256, 1) attn_kernel(
    const float* __restrict__ relx, const float* __restrict__ rely,
    float* __restrict__ out)
{
    extern __shared__ float4 sm4[];
    float* red  = (float*)(sm4 + SMEM_TILES_F4_);
    float* srel = red + 128 * RED_STRIDE_;

    const int t   = threadIdx.x;
    const int g   = t >> 6;          // group 0..3, owns chunks {2g, 2g+1}
    const int pid = t & 63;
    const int txh = pid & 7;         // pixel pair column 2*txh, 2*txh+1
    const int ty  = pid >> 3;
    const int b   = blockIdx.z;
    const int x0  = blockIdx.x * TW_, y0 = blockIdx.y * TH_;
    const int px0 = x0 + 2 * txh;
    const int py  = y0 + ty;

    if (t < 112) srel[t] = (t < 56) ? relx[t] : rely[t - 56];

    float4* tile = sm4 + g * (2 * TILE_F4_);
    const float* kb = g_qkv + MAT_STRIDE_;
    const float* vb = g_qkv + 2 * MAT_STRIDE_;

    cp_stage64(tile,            kb + (size_t)(b * NC_ + 2 * g    ) * CHUNK_STRIDE_, y0, x0, pid);
    cp_stage64(tile + TILE_F4_, kb + (size_t)(b * NC_ + 2 * g + 1) * CHUNK_STRIDE_, y0, x0, pid);
    cp_commit();
    cp_wait_all();
    group_bar(g);

    float l0[49], l1[49];
#pragma unroll
    for (int i = 0; i < 49; i++) { l0[i] = 0.f; l1[i] = 0.f; }
    float qx0[8], qy0[8], qx1[8], qy1[8];
#pragma unroll
    for (int i = 0; i < 8; i++) { qx0[i] = 0.f; qy0[i] = 0.f; qx1[i] = 0.f; qy1[i] = 0.f; }

    // ---- pass 1: partial logits for 2 adjacent pixels over 2 chunks ----
#pragma unroll 1
    for (int s = 0; s < 2; s++) {
        const float4* tp = tile + s * TILE_F4_;
        const float4* qp = (const float4*)(g_qkv +
            (size_t)(b * NC_ + 2 * g + s) * CHUNK_STRIDE_ +
            ((size_t)py * W_ + px0) * CC_);
        float4 qa[4] = {qp[0], qp[1], qp[2], qp[3]};
        float4 qb[4] = {qp[4], qp[5], qp[6], qp[7]};

        qx0[0] += qa[0].x; qx0[1] += qa[0].y; qx0[2] += qa[0].z; qx0[3] += qa[0].w;
        qx0[4] += qa[1].x; qx0[5] += qa[1].y; qx0[6] += qa[1].z; qx0[7] += qa[1].w;
        qy0[0] += qa[2].x; qy0[1] += qa[2].y; qy0[2] += qa[2].z; qy0[3] += qa[2].w;
        qy0[4] += qa[3].x; qy0[5] += qa[3].y; qy0[6] += qa[3].z; qy0[7] += qa[3].w;
        qx1[0] += qb[0].x; qx1[1] += qb[0].y; qx1[2] += qb[0].z; qx1[3] += qb[0].w;
        qx1[4] += qb[1].x; qx1[5] += qb[1].y; qx1[6] += qb[1].z; qx1[7] += qb[1].w;
        qy1[0] += qb[2].x; qy1[1] += qb[2].y; qy1[2] += qb[2].z; qy1[3] += qb[2].w;
        qy1[4] += qb[3].x; qy1[5] += qb[3].y; qy1[6] += qb[3].z; qy1[7] += qb[3].w;

#pragma unroll
        for (int r = 0; r < 7; r++) {
#pragma unroll
            for (int c = 0; c < 8; c++) {
                int o = (ty + r) * KW_ + 2 * txh + c;
                float4 k0 = tp[0 * PLANE_ + o];
                float4 k1 = tp[1 * PLANE_ + o];
                float4 k2 = tp[2 * PLANE_ + o];
                float4 k3 = tp[3 * PLANE_ + o];
                if (c < 7) l0[r * 7 + c]     = dot16(qa, k0, k1, k2, k3, l0[r * 7 + c]);
                if (c > 0) l1[r * 7 + c - 1] = dot16(qb, k0, k1, k2, k3, l1[r * 7 + c - 1]);
            }
        }
    }

    // group done with K -> stage V now; completes under the reduction
    group_bar(g);
    cp_stage64(tile,            vb + (size_t)(b * NC_ + 2 * g    ) * CHUNK_STRIDE_, y0, x0, pid);
    cp_stage64(tile + TILE_F4_, vb + (size_t)(b * NC_ + 2 * g + 1) * CHUNK_STRIDE_, y0, x0, pid);
    cp_commit();

    // ---- cross-group reduction (49 logits + 8 qx + 8 qy per pixel) ----
    float* rp0 = red + (2 * pid)     * RED_STRIDE_;
    float* rp1 = red + (2 * pid + 1) * RED_STRIDE_;
    __syncthreads();
    if (g == 0) {
#pragma unroll
        for (int j = 0; j < 49; j++) { rp0[j] = l0[j]; rp1[j] = l1[j]; }
#pragma unroll
        for (int j = 0; j < 8; j++) {
            rp0[49 + j] = qx0[j]; rp0[57 + j] = qy0[j];
            rp1[49 + j] = qx1[j]; rp1[57 + j] = qy1[j];
        }
    }
    __syncthreads();
    if (g == 1) {
#pragma unroll
        for (int j = 0; j < 49; j++) { rp0[j] += l0[j]; rp1[j] += l1[j]; }
#pragma unroll
        for (int j = 0; j < 8; j++) {
            rp0[49 + j] += qx0[j]; rp0[57 + j] += qy0[j];
            rp1[49 + j] += qx1[j]; rp1[57 + j] += qy1[j];
        }
    }
    __syncthreads();
    if (g == 2) {
#pragma unroll
        for (int j = 0; j < 49; j++) { rp0[j] += l0[j]; rp1[j] += l1[j]; }
#pragma unroll
        for (int j = 0; j < 8; j++) {
            rp0[49 + j] += qx0[j]; rp0[57 + j] += qy0[j];
            rp1[49 + j] += qx1[j]; rp1[57 + j] += qy1[j];
        }
    }
    __syncthreads();
    if (g == 3) {
#pragma unroll
        for (int j = 0; j < 49; j++) { rp0[j] += l0[j]; rp1[j] += l1[j]; }
#pragma unroll
        for (int j = 0; j < 8; j++) {
            rp0[49 + j] += qx0[j]; rp0[57 + j] += qy0[j];
            rp1[49 + j] += qx1[j]; rp1[57 + j] += qy1[j];
        }
    }
    __syncthreads();
#pragma unroll
    for (int j = 0; j < 49; j++) { l0[j] = rp0[j]; l1[j] = rp1[j]; }
#pragma unroll
    for (int j = 0; j < 8; j++) {
        qx0[j] = rp0[49 + j]; qy0[j] = rp0[57 + j];
        qx1[j] = rp1[49 + j]; qy1[j] = rp1[57 + j];
    }

    // ---- bias + softmax for both pixels ----
#pragma unroll
    for (int p = 0; p < 2; p++) {
        float* l  = p ? l1 : l0;
        float* qx = p ? qx1 : qx0;
        float* qy = p ? qy1 : qy0;
        float bx[7], by[7];
#pragma unroll
        for (int kj = 0; kj < 7; kj++) {
            float s = 0.f;
#pragma unroll
            for (int xi = 0; xi < 8; xi++) s = fmaf(qx[xi], srel[xi * 7 + kj], s);
            bx[kj] = s;
        }
#pragma unroll
        for (int ki = 0; ki < 7; ki++) {
            float s = 0.f;
#pragma unroll
            for (int yi = 0; yi < 8; yi++) s = fmaf(qy[yi], srel[56 + yi * 7 + ki], s);
            by[ki] = s;
        }
        float m = -1e30f;
#pragma unroll
        for (int ki = 0; ki < 7; ki++)
#pragma unroll
            for (int kj = 0; kj < 7; kj++) {
                float v = l[ki * 7 + kj] + bx[kj] + by[ki];
                l[ki * 7 + kj] = v;
                m = fmaxf(m, v);
            }
        float ssum = 0.f;
#pragma unroll
        for (int i = 0; i < 49; i++) { float e = __expf(l[i] - m); l[i] = e; ssum += e; }
        float inv = 1.f / ssum;
#pragma unroll
        for (int i = 0; i < 49; i++) l[i] *= inv;
    }

    // ---- pass 2: V (already staged); 2 px share row loads ----
    cp_wait_all();
    group_bar(g);

#pragma unroll 1
    for (int s = 0; s < 2; s++) {
        const float4* tp = tile + s * TILE_F4_;
        float4 oa[4], ob[4];
#pragma unroll
        for (int i = 0; i < 4; i++) {
            oa[i] = make_float4(0.f, 0.f, 0.f, 0.f);
            ob[i] = make_float4(0.f, 0.f, 0.f, 0.f);
        }
#pragma unroll
        for (int r = 0; r < 7; r++) {
#pragma unroll
            for (int c = 0; c < 8; c++) {
                int o = (ty + r) * KW_ + 2 * txh + c;
                float4 v0 = tp[0 * PLANE_ + o];
                float4 v1 = tp[1 * PLANE_ + o];
                float4 v2 = tp[2 * PLANE_ + o];
                float4 v3 = tp[3 * PLANE_ + o];
                if (c < 7) {
                    float a = l0[r * 7 + c];
                    oa[0].x = fmaf(a, v0.x, oa[0].x); oa[0].y = fmaf(a, v0.y, oa[0].y);
                    oa[0].z = fmaf(a, v0.z, oa[0].z); oa[0].w = fmaf(a, v0.w, oa[0].w);
                    oa[1].x = fmaf(a, v1.x, oa[1].x); oa[1].y = fmaf(a, v1.y, oa[1].y);
                    oa[1].z = fmaf(a, v1.z, oa[1].z); oa[1].w = fmaf(a, v1.w, oa[1].w);
                    oa[2].x = fmaf(a, v2.x, oa[2].x); oa[2].y = fmaf(a, v2.y, oa[2].y);
                    oa[2].z = fmaf(a, v2.z, oa[2].z); oa[2].w = fmaf(a, v2.w, oa[2].w);
                    oa[3].x = fmaf(a, v3.x, oa[3].x); oa[3].y = fmaf(a, v3.y, oa[3].y);
                    oa[3].z = fmaf(a, v3.z, oa[3].z); oa[3].w = fmaf(a, v3.w, oa[3].w);
                }
                if (c > 0) {
                    float a = l1[r * 7 + c - 1];
                    ob[0].x = fmaf(a, v0.x, ob[0].x); ob[0].y = fmaf(a, v0.y, ob[0].y);
                    ob[0].z = fmaf(a, v0.z, ob[0].z); ob[0].w = fmaf(a, v0.w, ob[0].w);
                    ob[1].x = fmaf(a, v1.x, ob[1].x); ob[1].y = fmaf(a, v1.y, ob[1].y);
                    ob[1].z = fmaf(a, v1.z, ob[1].z); ob[1].w = fmaf(a, v1.w, ob[1].w);
                    ob[2].x = fmaf(a, v2.x, ob[2].x); ob[2].y = fmaf(a, v2.y, ob[2].y);
                    ob[2].z = fmaf(a, v2.z, ob[2].z); ob[2].w = fmaf(a, v2.w, ob[2].w);
                    ob[3].x = fmaf(a, v3.x, ob[3].x); ob[3].y = fmaf(a, v3.y, ob[3].y);
                    ob[3].z = fmaf(a, v3.z, ob[3].z); ob[3].w = fmaf(a, v3.w, ob[3].w);
                }
            }
        }
        int cch = 2 * g + s;   // chunk -> output channels cch*16 .. +15
        size_t obase = ((size_t)(b * C_ + cch * CC_) * H_ + py) * W_ + px0;
        float av[16] = {oa[0].x,oa[0].y,oa[0].z,oa[0].w, oa[1].x,oa[1].y,oa[1].z,oa[1].w,
                        oa[2].x,oa[2].y,oa[2].z,oa[2].w, oa[3].x,oa[3].y,oa[3].z,oa[3].w};
        float bv[16] = {ob[0].x,ob[0].y,ob[0].z,ob[0].w, ob[1].x,ob[1].y,ob[1].z,ob[1].w,
                        ob[2].x,ob[2].y,ob[2].z,ob[2].w, ob[3].x,ob[3].y,ob[3].z,ob[3].w};
#pragma unroll
        for (int cch2 = 0; cch2 < 16; cch2++)
            *(float2*)(out + obase + (size_t)cch2 * HW_) = make_float2(av[cch2], bv[cch2]);
    }
}

// ---------------- launch -----------------------------------------------------
extern "C" void kernel_launch(void* const* d_in, const int* in_sizes, int n_in,
                              void* d_out, int out_size)
{
    const float* x    = (const float*)d_in[0];
    const float* wq   = (const float*)d_in[1];
    const float* wk   = (const float*)d_in[2];
    const float* wv   = (const float*)d_in[3];
    const float* relx = (const float*)d_in[4];
    const float* rely = (const float*)d_in[5];
    float* out = (float*)d_out;

    cudaFuncSetAttribute(proj_mma_kernel,
                         cudaFuncAttributeMaxDynamicSharedMemorySize, PSM_BYTES_);
    cudaFuncSetAttribute(attn_kernel,
                         cudaFuncAttributeMaxDynamicSharedMemorySize, SMEM_BYTES_);

    proj_mma_kernel<<<dim3(64, B_), 256, PSM_BYTES_>>>(x, wq, wk, wv);
    attn_kernel<<<dim3(W_ / TW_, H_ / TH_, B_), 256, SMEM_BYTES_>>>(relx, rely, out);
}

// round 14
// speedup vs baseline: 1.0478x; 1.0478x over previous
#include <cuda_runtime.h>
#include <cuda_bf16.h>
#include <cstdint>

#define B_   4
#define C_   128
#define H_   64
#define W_   64
#define KS_  7
#define PAD_ 3
#define NC_  8      // channel chunks
#define CC_  16     // channels per chunk ( == O/GROUPS )
#define HW_  (H_*W_)

#define CHUNK_STRIDE_ ((size_t)H_*W_*CC_)            // per (b,cc) plane
#define MAT_STRIDE_   ((size_t)B_*NC_*H_*W_*CC_)     // per q/k/v matrix

// Scratch for q,k,v in chunked pixel-major layout: [mat][b][cc][y][x][16]
__device__ __align__(16) float g_qkv[3ull * B_ * NC_ * H_ * W_ * CC_];

// Pre-split bf16 W images in the padded [n][136] SMEM layout: [mat][hi/lo]
#define WLDH_ 136
__device__ __align__(16) unsigned short g_w16[3][2][128 * WLDH_];

// ================= common helpers =================
__device__ __forceinline__ uint32_t smem_u32(const void* p) {
    uint32_t a;
    asm("{ .reg .u64 t; cvta.to.shared.u64 t, %1; cvt.u32.u64 %0, t; }"
        : "=r"(a) : "l"(p));
    return a;
}
__device__ __forceinline__ void ldsm_x4_trans(uint32_t* r, uint32_t addr) {
    asm volatile("ldmatrix.sync.aligned.m8n8.x4.trans.shared.b16 {%0,%1,%2,%3}, [%4];"
                 : "=r"(r[0]), "=r"(r[1]), "=r"(r[2]), "=r"(r[3]) : "r"(addr));
}
__device__ __forceinline__ void ldsm_x2(uint32_t& b0, uint32_t& b1, uint32_t addr) {
    asm volatile("ldmatrix.sync.aligned.m8n8.x2.shared.b16 {%0,%1}, [%2];"
                 : "=r"(b0), "=r"(b1) : "r"(addr));
}
__device__ __forceinline__ void mma16816(float* d, const uint32_t* a,
                                         uint32_t b0, uint32_t b1) {
    asm volatile(
        "mma.sync.aligned.m16n8k16.row.col.f32.bf16.bf16.f32 "
        "{%0,%1,%2,%3}, {%4,%5,%6,%7}, {%8,%9}, {%0,%1,%2,%3};"
        : "+f"(d[0]), "+f"(d[1]), "+f"(d[2]), "+f"(d[3])
        : "r"(a[0]), "r"(a[1]), "r"(a[2]), "r"(a[3]), "r"(b0), "r"(b1));
}
__device__ __forceinline__ void split4(float4 v, uint2& hi, uint2& lo) {
    float vv[4] = {v.x, v.y, v.z, v.w};
    unsigned short h[4], l[4];
#pragma unroll
    for (int e = 0; e < 4; e++) {
        __nv_bfloat16 hb = __float2bfloat16(vv[e]);
        __nv_bfloat16 lb = __float2bfloat16(vv[e] - __bfloat162float(hb));
        h[e] = __bfloat16_as_ushort(hb);
        l[e] = __bfloat16_as_ushort(lb);
    }
    hi = make_uint2((uint32_t)h[0] | ((uint32_t)h[1] << 16),
                    (uint32_t)h[2] | ((uint32_t)h[3] << 16));
    lo = make_uint2((uint32_t)l[0] | ((uint32_t)l[1] << 16),
                    (uint32_t)l[2] | ((uint32_t)l[3] << 16));
}
__device__ __forceinline__ void cp_commit() {
    asm volatile("cp.async.commit_group;" ::: "memory");
}
__device__ __forceinline__ void cp_wait_all() {
    asm volatile("cp.async.wait_all;" ::: "memory");
}
template <int N>
__device__ __forceinline__ void cp_wait_group() {
    asm volatile("cp.async.wait_group %0;" :: "n"(N) : "memory");
}
__device__ __forceinline__ void cp16(uint32_t daddr, const void* src) {
    asm volatile("cp.async.cg.shared.global [%0], [%1], 16;"
                 :: "r"(daddr), "l"(src));
}

// ---------------- Kernel 0: parallel W -> split-bf16 padded images -----------
// grid (3 mats, 16 segs of 8 rows), 256 threads: 1 float4 per thread.
__global__ __launch_bounds__(256) void wprep_kernel(
    const float* __restrict__ wq, const float* __restrict__ wk,
    const float* __restrict__ wv)
{
    const int mat = blockIdx.x, seg = blockIdx.y;
    const float* w = (mat == 0) ? wq : (mat == 1) ? wk : wv;
    const int t = threadIdx.x;
    int n  = seg * 8 + (t >> 5);      // row
    int k4 = t & 31;                  // k quad
    float4 v = *(const float4*)(w + n * 128 + k4 * 4);
    uint2 hi, lo; split4(v, hi, lo);
    uint32_t off = (uint32_t)(n * WLDH_ + k4 * 4);
    *(uint2*)&g_w16[mat][0][off] = hi;
    *(uint2*)&g_w16[mat][1][off] = lo;
}

// ---------------- Kernel 1: QKV projection, double-buffered W cp.async -------
// grid = (64 px-tiles of 64px, 4 batches); 256 threads; 1 CTA/SM (172 KB).
#define PALD_ 72                               // A pitch in halfs (144 B rows)
#define PSA_HI_ 0
#define PSA_LO_ (PSA_HI_ + 128 * PALD_ * 2)    // 18432
#define PWA_    (PSA_LO_ + 128 * PALD_ * 2)    // 36864  (end of A)
#define WIMG_   (128 * WLDH_ * 2)              // 34816  (one hi or lo image)
#define WPAIR_  (2 * WIMG_)                    // 69632  (hi+lo pair)
#define PSM_BYTES_ (PWA_ + 2 * WPAIR_)         // 176128 -> 1 CTA/SM

__global__ void __launch_bounds__(256, 1) proj_mma_kernel(const float* __restrict__ x)
{
    extern __shared__ char sm[];
    const uint32_t smb = smem_u32(sm);
    const int t = threadIdx.x;
    const int pxbase = blockIdx.x * 64;
    const int b = blockIdx.y;

    // ---- prologue: issue W0 and W1 image copies (byte-exact, cp.async) ----
#pragma unroll 1
    for (int buf = 0; buf < 2; buf++) {
        const char* src = (const char*)g_w16[buf];    // mat == buf for first two
        uint32_t dst = smb + PWA_ + buf * WPAIR_;
#pragma unroll
        for (int i = 0; i < 17; i++) {
            int idx = t + i * 256;                    // 4352 float4 per pair
            if (idx < WPAIR_ / 16)
                cp16(dst + idx * 16, src + idx * 16);
        }
        cp_commit();
    }

    // ---- X tile: load [128ch][64px], split bf16, store [ch][px] ----
#pragma unroll
    for (int j = 0; j < 8; j++) {
        int idx = t + j * 256;
        int c  = idx >> 4;
        int p4 = idx & 15;
        float4 v = *(const float4*)(x + ((size_t)(b * C_ + c)) * HW_ + pxbase + p4 * 4);
        uint2 hi, lo; split4(v, hi, lo);
        uint32_t off = (uint32_t)(c * PALD_ + p4 * 4) * 2;
        *(uint2*)(sm + PSA_HI_ + off) = hi;
        *(uint2*)(sm + PSA_LO_ + off) = lo;
    }

    const int w = t >> 5, lane = t & 31;
    const int m0 = (w & 1) * 32;
    const int n0 = (w >> 1) * 32;
    const int lq = lane & 15;

    const uint32_t a_base = smb + PSA_HI_ +
        (uint32_t)(((lane & 7) + ((lane >> 4) & 1) * 8) * PALD_ +
                   (m0 + ((lane >> 3) & 1) * 8)) * 2;
    const uint32_t b_off = (uint32_t)((n0 + (lq & 7)) * WLDH_) * 2 + ((lq >> 3) & 1) * 16;

#pragma unroll 1
    for (int mat = 0; mat < 3; mat++) {
        // wait for this mat's W images (FIFO; leaves the next copy in flight)
        if (mat < 2) cp_wait_group<1>(); else cp_wait_group<0>();
        __syncthreads();

        const uint32_t wbuf = smb + PWA_ + (mat % 2) * WPAIR_;
        const uint32_t b_base = wbuf + b_off;

        float acc[2][4][4];
#pragma unroll
        for (int mt = 0; mt < 2; mt++)
#pragma unroll
            for (int nt = 0; nt < 4; nt++)
#pragma unroll
                for (int e = 0; e < 4; e++) acc[mt][nt][e] = 0.f;

#pragma unroll
        for (int ks = 0; ks < 8; ks++) {
            uint32_t ahi[2][4], alo[2][4];
#pragma unroll
            for (int mt = 0; mt < 2; mt++) {
                uint32_t aa = a_base + (uint32_t)(ks * 16 * PALD_ * 2 + mt * 32);
                ldsm_x4_trans(ahi[mt], aa);
                ldsm_x4_trans(alo[mt], aa + (PSA_LO_ - PSA_HI_));
            }
#pragma unroll
            for (int nt = 0; nt < 4; nt++) {
                uint32_t ba = b_base + (uint32_t)(nt * 8 * WLDH_ * 2 + ks * 32);
                uint32_t bh0, bh1, bl0, bl1;
                ldsm_x2(bh0, bh1, ba);
                ldsm_x2(bl0, bl1, ba + WIMG_);
#pragma unroll
                for (int mt = 0; mt < 2; mt++) {
                    mma16816(acc[mt][nt], ahi[mt], bh0, bh1);
                    mma16816(acc[mt][nt], ahi[mt], bl0, bl1);
                    mma16816(acc[mt][nt], alo[mt], bh0, bh1);
                }
            }
        }

        // ---- epilogue ----
#pragma unroll
        for (int mt = 0; mt < 2; mt++) {
#pragma unroll
            for (int nt = 0; nt < 4; nt++) {
                int nn = n0 + nt * 8 + (lane & 3) * 2;
                int cc = nn >> 4, ch16 = nn & 15;
                int flat = pxbase + m0 + mt * 16 + (lane >> 2);
                float* dst = g_qkv + (size_t)mat * MAT_STRIDE_ +
                             (size_t)(b * NC_ + cc) * CHUNK_STRIDE_ +
                             (size_t)flat * 16 + ch16;
                *(float2*)dst          = make_float2(acc[mt][nt][0], acc[mt][nt][1]);
                *(float2*)(dst + 128)  = make_float2(acc[mt][nt][2], acc[mt][nt][3]);
            }
        }
        __syncthreads();    // all reads of buf(mat%2) done

        // issue W2 into buf0 behind mat0's MMA
        if (mat == 0) {
            const char* src = (const char*)g_w16[2];
            uint32_t dst = smb + PWA_;               // buf0
#pragma unroll
            for (int i = 0; i < 17; i++) {
                int idx = t + i * 256;
                if (idx < WPAIR_ / 16)
                    cp16(dst + idx * 16, src + idx * 16);
            }
            cp_commit();
        }
    }
}

// ---------------- Kernel 2: windowed attention (proven R5 design) ------------
#define TW_ 16
#define TH_ 8
#define KW_ (TW_ + KS_ - 1)        // 22
#define KH_ (TH_ + KS_ - 1)        // 14
#define NGR_ 4
#define PLANE_ (KH_ * KW_)          // 308
#define TILE_F4_ (4 * PLANE_)       // 1232
#define RED_STRIDE_ 65
#define SMEM_TILES_F4_ (NGR_ * 2 * TILE_F4_)
#define SMEM_BYTES_ (SMEM_TILES_F4_ * 16 + 128 * RED_STRIDE_ * 4 + 112 * 4)

__device__ __forceinline__ void cp_stage(float4* __restrict__ dst,
                                         const float* __restrict__ base,
                                         int y0, int x0, int pid)
{
#pragma unroll
    for (int it = 0; it < 10; it++) {
        int i = pid + it * 128;
        if (i < TILE_F4_) {
            int c4  = i / PLANE_;
            int rem = i - c4 * PLANE_;
            int yy  = rem / KW_;
            int xx  = rem - yy * KW_;
            int gy = y0 - PAD_ + yy, gx = x0 - PAD_ + xx;
            bool inb = ((unsigned)gy < H_) && ((unsigned)gx < W_);
            const float* src = base + ((size_t)(inb ? gy : 0) * W_ + (inb ? gx : 0)) * CC_ + c4 * 4;
            unsigned daddr = (unsigned)__cvta_generic_to_shared(dst + i);
            int sz = inb ? 16 : 0;
            asm volatile("cp.async.cg.shared.global [%0], [%1], 16, %2;"
                         :: "r"(daddr), "l"(src), "r"(sz));
        }
    }
}
__device__ __forceinline__ void group_bar(int g) {
    asm volatile("bar.sync %0, %1;" :: "r"(1 + g), "r"(128) : "memory");
}

__global__ void __launch_bounds__(512, 1) attn_kernel(
    const float* __restrict__ relx, const float* __restrict__ rely,
    float* __restrict__ out)
{
    extern __shared__ float4 sm4[];
    float* red  = (float*)(sm4 + SMEM_TILES_F4_);
    float* srel = red + 128 * RED_STRIDE_;

    const int t   = threadIdx.x;
    const int g   = t >> 7;
    const int pid = t & 127;
    const int tx  = pid & 15, ty = pid >> 4;
    const int b   = blockIdx.z;
    const int x0  = blockIdx.x * TW_, y0 = blockIdx.y * TH_;
    const int px  = x0 + tx, py = y0 + ty;

    if (t < 112) srel[t] = (t < 56) ? relx[t] : rely[t - 56];

    float4* tile = sm4 + g * (2 * TILE_F4_);
    const float* kb = g_qkv + MAT_STRIDE_;
    const float* vb = g_qkv + 2 * MAT_STRIDE_;

    cp_stage(tile,            kb + (size_t)(b * NC_ + 2 * g    ) * CHUNK_STRIDE_, y0, x0, pid);
    cp_stage(tile + TILE_F4_, kb + (size_t)(b * NC_ + 2 * g + 1) * CHUNK_STRIDE_, y0, x0, pid);
    cp_commit();
    cp_wait_all();
    group_bar(g);

    float logit[49];
#pragma unroll
    for (int i = 0; i < 49; i++) logit[i] = 0.f;
    float qxs[8], qys[8];
#pragma unroll
    for (int i = 0; i < 8; i++) { qxs[i] = 0.f; qys[i] = 0.f; }

#pragma unroll 1
    for (int s = 0; s < 2; s++) {
        const float4* tp = tile + s * TILE_F4_;
        const float4* qp = (const float4*)(g_qkv +
            (size_t)(b * NC_ + 2 * g + s) * CHUNK_STRIDE_ +
            ((size_t)py * W_ + px) * CC_);
        float4 q0 = qp[0], q1 = qp[1], q2 = qp[2], q3 = qp[3];

        qxs[0] += q0.x; qxs[1] += q0.y; qxs[2] += q0.z; qxs[3] += q0.w;
        qxs[4] += q1.x; qxs[5] += q1.y; qxs[6] += q1.z; qxs[7] += q1.w;
        qys[0] += q2.x; qys[1] += q2.y; qys[2] += q2.z; qys[3] += q2.w;
        qys[4] += q3.x; qys[5] += q3.y; qys[6] += q3.z; qys[7] += q3.w;

#pragma unroll
        for (int ki = 0; ki < KS_; ki++) {
#pragma unroll
            for (int kj = 0; kj < KS_; kj++) {
                int o = (ty + ki) * KW_ + tx + kj;
                float4 k0 = tp[0 * PLANE_ + o];
                float4 k1 = tp[1 * PLANE_ + o];
                float4 k2 = tp[2 * PLANE_ + o];
                float4 k3 = tp[3 * PLANE_ + o];
                float sacc = logit[ki * KS_ + kj];
                sacc = fmaf(q0.x, k0.x, sacc); sacc = fmaf(q0.y, k0.y, sacc);
                sacc = fmaf(q0.z, k0.z, sacc); sacc = fmaf(q0.w, k0.w, sacc);
                sacc = fmaf(q1.x, k1.x, sacc); sacc = fmaf(q1.y, k1.y, sacc);
                sacc = fmaf(q1.z, k1.z, sacc); sacc = fmaf(q1.w, k1.w, sacc);
                sacc = fmaf(q2.x, k2.x, sacc); sacc = fmaf(q2.y, k2.y, sacc);
                sacc = fmaf(q2.z, k2.z, sacc); sacc = fmaf(q2.w, k2.w, sacc);
                sacc = fmaf(q3.x, k3.x, sacc); sacc = fmaf(q3.y, k3.y, sacc);
                sacc = fmaf(q3.z, k3.z, sacc); sacc = fmaf(q3.w, k3.w, sacc);
                logit[ki * KS_ + kj] = sacc;
            }
        }
    }

    group_bar(g);
    cp_stage(tile,            vb + (size_t)(b * NC_ + 2 * g    ) * CHUNK_STRIDE_, y0, x0, pid);
    cp_stage(tile + TILE_F4_, vb + (size_t)(b * NC_ + 2 * g + 1) * CHUNK_STRIDE_, y0, x0, pid);
    cp_commit();

    float* rp = red + pid * RED_STRIDE_;
    __syncthreads();
    if (g == 0) {
#pragma unroll
        for (int j = 0; j < 49; j++) rp[j] = logit[j];
#pragma unroll
        for (int j = 0; j < 8; j++) { rp[49 + j] = qxs[j]; rp[57 + j] = qys[j]; }
    }
    __syncthreads();
    if (g == 1) {
#pragma unroll
        for (int j = 0; j < 49; j++) rp[j] += logit[j];
#pragma unroll
        for (int j = 0; j < 8; j++) { rp[49 + j] += qxs[j]; rp[57 + j] += qys[j]; }
    }
    __syncthreads();
    if (g == 2) {
#pragma unroll
        for (int j = 0; j < 49; j++) rp[j] += logit[j];
#pragma unroll
        for (int j = 0; j < 8; j++) { rp[49 + j] += qxs[j]; rp[57 + j] += qys[j]; }
    }
    __syncthreads();
    if (g == 3) {
#pragma unroll
        for (int j = 0; j < 49; j++) rp[j] += logit[j];
#pragma unroll
        for (int j = 0; j < 8; j++) { rp[49 + j] += qxs[j]; rp[57 + j] += qys[j]; }
    }
    __syncthreads();
#pragma unroll
    for (int j = 0; j < 49; j++) logit[j] = rp[j];
#pragma unroll
    for (int j = 0; j < 8; j++) { qxs[j] = rp[49 + j]; qys[j] = rp[57 + j]; }

    float bxv[7], byv[7];
#pragma unroll
    for (int kj = 0; kj < 7; kj++) {
        float s = 0.f;
#pragma unroll
        for (int xi = 0; xi < 8; xi++) s = fmaf(qxs[xi], srel[xi * 7 + kj], s);
        bxv[kj] = s;
    }
#pragma unroll
    for (int ki = 0; ki < 7; ki++) {
        float s = 0.f;
#pragma unroll
        for (int yi = 0; yi < 8; yi++) s = fmaf(qys[yi], srel[56 + yi * 7 + ki], s);
        byv[ki] = s;
    }
    float m = -1e30f;
#pragma unroll
    for (int ki = 0; ki < 7; ki++)
#pragma unroll
        for (int kj = 0; kj < 7; kj++) {
            float l = logit[ki * 7 + kj] + bxv[kj] + byv[ki];
            logit[ki * 7 + kj] = l;
            m = fmaxf(m, l);
        }
    float ssum = 0.f;
#pragma unroll
    for (int i = 0; i < 49; i++) {
        float e = __expf(logit[i] - m);
        logit[i] = e;
        ssum += e;
    }
    float inv = 1.f / ssum;
#pragma unroll
    for (int i = 0; i < 49; i++) logit[i] *= inv;

    cp_wait_all();
    group_bar(g);

#pragma unroll 1
    for (int s = 0; s < 2; s++) {
        const float4* tp = tile + s * TILE_F4_;
        float4 o0 = make_float4(0.f, 0.f, 0.f, 0.f), o1 = o0, o2 = o0, o3 = o0;
#pragma unroll
        for (int ki = 0; ki < KS_; ki++) {
#pragma unroll
            for (int kj = 0; kj < KS_; kj++) {
                float a = logit[ki * KS_ + kj];
                int o = (ty + ki) * KW_ + tx + kj;
                float4 v0 = tp[0 * PLANE_ + o];
                float4 v1 = tp[1 * PLANE_ + o];
                float4 v2 = tp[2 * PLANE_ + o];
                float4 v3 = tp[3 * PLANE_ + o];
                o0.x = fmaf(a, v0.x, o0.x); o0.y = fmaf(a, v0.y, o0.y);
                o0.z = fmaf(a, v0.z, o0.z); o0.w = fmaf(a, v0.w, o0.w);
                o1.x = fmaf(a, v1.x, o1.x); o1.y = fmaf(a, v1.y, o1.y);
                o1.z = fmaf(a, v1.z, o1.z); o1.w = fmaf(a, v1.w, o1.w);
                o2.x = fmaf(a, v2.x, o2.x); o2.y = fmaf(a, v2.y, o2.y);
                o2.z = fmaf(a, v2.z, o2.z); o2.w = fmaf(a, v2.w, o2.w);
                o3.x = fmaf(a, v3.x, o3.x); o3.y = fmaf(a, v3.y, o3.y);
                o3.z = fmaf(a, v3.z, o3.z); o3.w = fmaf(a, v3.w, o3.w);
            }
        }
        int c = 2 * g + s;
        size_t ob = ((size_t)(b * C_ + c * CC_) * H_ + py) * W_ + px;
        out[ob +  0 * HW_] = o0.x; out[ob +  1 * HW_] = o0.y;
        out[ob +  2 * HW_] = o0.z; out[ob +  3 * HW_] = o0.w;
        out[ob +  4 * HW_] = o1.x; out[ob +  5 * HW_] = o1.y;
        out[ob +  6 * HW_] = o1.z; out[ob +  7 * HW_] = o1.w;
        out[ob +  8 * HW_] = o2.x; out[ob +  9 * HW_] = o2.y;
        out[ob + 10 * HW_] = o2.z; out[ob + 11 * HW_] = o2.w;
        out[ob + 12 * HW_] = o3.x; out[ob + 13 * HW_] = o3.y;
        out[ob + 14 * HW_] = o3.z; out[ob + 15 * HW_] = o3.w;
    }
}

// ---------------- launch -----------------------------------------------------
extern "C" void kernel_launch(void* const* d_in, const int* in_sizes, int n_in,
                              void* d_out, int out_size)
{
    const float* x    = (const float*)d_in[0];
    const float* wq   = (const float*)d_in[1];
    const float* wk   = (const float*)d_in[2];
    const float* wv   = (const float*)d_in[3];
    const float* relx = (const float*)d_in[4];
    const float* rely = (const float*)d_in[5];
    float* out = (float*)d_out;

    cudaFuncSetAttribute(proj_mma_kernel,
                         cudaFuncAttributeMaxDynamicSharedMemorySize, PSM_BYTES_);
    cudaFuncSetAttribute(attn_kernel,
                         cudaFuncAttributeMaxDynamicSharedMemorySize, SMEM_BYTES_);

    wprep_kernel<<<dim3(3, 16), 256>>>(wq, wk, wv);
    proj_mma_kernel<<<dim3(64, B_), 256, PSM_BYTES_>>>(x);
    attn_kernel<<<dim3(W_ / TW_, H_ / TH_, B_), 512, SMEM_BYTES_>>>(relx, rely, out);
}

// round 15
// speedup vs baseline: 1.0858x; 1.0363x over previous
#include <cuda_runtime.h>
#include <cuda_bf16.h>
#include <cstdint>

#define B_   4
#define C_   128
#define H_   64
#define W_   64
#define KS_  7
#define PAD_ 3
#define NC_  8      // channel chunks
#define CC_  16     // channels per chunk ( == O/GROUPS )
#define HW_  (H_*W_)

#define CHUNK_STRIDE_ ((size_t)H_*W_*CC_)            // per (b,cc) plane
#define MAT_STRIDE_   ((size_t)B_*NC_*H_*W_*CC_)     // per q/k/v matrix

// Scratch for q,k,v in chunked pixel-major layout: [mat][b][cc][y][x][16]
__device__ __align__(16) float g_qkv[3ull * B_ * NC_ * H_ * W_ * CC_];

// Pre-split bf16 W images in the padded [n][136] SMEM layout: [mat][hi/lo]
#define WLDH_ 136
__device__ __align__(16) unsigned short g_w16[3][2][128 * WLDH_];

// ================= common helpers =================
__device__ __forceinline__ uint32_t smem_u32(const void* p) {
    uint32_t a;
    asm("{ .reg .u64 t; cvta.to.shared.u64 t, %1; cvt.u32.u64 %0, t; }"
        : "=r"(a) : "l"(p));
    return a;
}
__device__ __forceinline__ void ldsm_x4_trans(uint32_t* r, uint32_t addr) {
    asm volatile("ldmatrix.sync.aligned.m8n8.x4.trans.shared.b16 {%0,%1,%2,%3}, [%4];"
                 : "=r"(r[0]), "=r"(r[1]), "=r"(r[2]), "=r"(r[3]) : "r"(addr));
}
__device__ __forceinline__ void ldsm_x2(uint32_t& b0, uint32_t& b1, uint32_t addr) {
    asm volatile("ldmatrix.sync.aligned.m8n8.x2.shared.b16 {%0,%1}, [%2];"
                 : "=r"(b0), "=r"(b1) : "r"(addr));
}
__device__ __forceinline__ void mma16816(float* d, const uint32_t* a,
                                         uint32_t b0, uint32_t b1) {
    asm volatile(
        "mma.sync.aligned.m16n8k16.row.col.f32.bf16.bf16.f32 "
        "{%0,%1,%2,%3}, {%4,%5,%6,%7}, {%8,%9}, {%0,%1,%2,%3};"
        : "+f"(d[0]), "+f"(d[1]), "+f"(d[2]), "+f"(d[3])
        : "r"(a[0]), "r"(a[1]), "r"(a[2]), "r"(a[3]), "r"(b0), "r"(b1));
}
__device__ __forceinline__ void split4(float4 v, uint2& hi, uint2& lo) {
    float vv[4] = {v.x, v.y, v.z, v.w};
    unsigned short h[4], l[4];
#pragma unroll
    for (int e = 0; e < 4; e++) {
        __nv_bfloat16 hb = __float2bfloat16(vv[e]);
        __nv_bfloat16 lb = __float2bfloat16(vv[e] - __bfloat162float(hb));
        h[e] = __bfloat16_as_ushort(hb);
        l[e] = __bfloat16_as_ushort(lb);
    }
    hi = make_uint2((uint32_t)h[0] | ((uint32_t)h[1] << 16),
                    (uint32_t)h[2] | ((uint32_t)h[3] << 16));
    lo = make_uint2((uint32_t)l[0] | ((uint32_t)l[1] << 16),
                    (uint32_t)l[2] | ((uint32_t)l[3] << 16));
}
__device__ __forceinline__ void cp_commit() {
    asm volatile("cp.async.commit_group;" ::: "memory");
}
__device__ __forceinline__ void cp_wait_all() {
    asm volatile("cp.async.wait_all;" ::: "memory");
}
__device__ __forceinline__ void cp16(uint32_t daddr, const void* src) {
    asm volatile("cp.async.cg.shared.global [%0], [%1], 16;"
                 :: "r"(daddr), "l"(src));
}

// ---------------- Kernel 0: parallel W -> split-bf16 padded images -----------
__global__ __launch_bounds__(256) void wprep_kernel(
    const float* __restrict__ wq, const float* __restrict__ wk,
    const float* __restrict__ wv)
{
    const int mat = blockIdx.x, seg = blockIdx.y;
    const float* w = (mat == 0) ? wq : (mat == 1) ? wk : wv;
    const int t = threadIdx.x;
    int n  = seg * 8 + (t >> 5);      // row
    int k4 = t & 31;                  // k quad
    float4 v = *(const float4*)(w + n * 128 + k4 * 4);
    uint2 hi, lo; split4(v, hi, lo);
    uint32_t off = (uint32_t)(n * WLDH_ + k4 * 4);
    *(uint2*)&g_w16[mat][0][off] = hi;
    *(uint2*)&g_w16[mat][1][off] = lo;
}

// ---------------- Kernel 1: QKV projection, single-buffer W, 2 CTAs/SM -------
// grid = (64 px-tiles of 64px, 4 batches); 256 threads.
#define PALD_ 72                               // A pitch in halfs (144 B rows)
#define PSA_HI_ 0
#define PSA_LO_ (PSA_HI_ + 128 * PALD_ * 2)    // 18432
#define PWA_    (PSA_LO_ + 128 * PALD_ * 2)    // 36864  (end of A)
#define WIMG_   (128 * WLDH_ * 2)              // 34816  (one hi or lo image)
#define WPAIR_  (2 * WIMG_)                    // 69632  (hi+lo pair)
#define PSM_BYTES_ (PWA_ + WPAIR_)             // 106496 -> 2 CTAs/SM

__global__ void __launch_bounds__(256, 2) proj_mma_kernel(const float* __restrict__ x)
{
    extern __shared__ char sm[];
    const uint32_t smb = smem_u32(sm);
    const int t = threadIdx.x;
    const int pxbase = blockIdx.x * 64;
    const int b = blockIdx.y;

    // ---- prologue: issue W0 image copy; overlapped by X conversion ----
    {
        const char* src = (const char*)g_w16[0];
        uint32_t dst = smb + PWA_;
#pragma unroll
        for (int i = 0; i < 17; i++) {
            int idx = t + i * 256;                    // 4352 float4 per pair
            if (idx < WPAIR_ / 16)
                cp16(dst + idx * 16, src + idx * 16);
        }
        cp_commit();
    }

    // ---- X tile: load [128ch][64px], split bf16, store [ch][px] ----
#pragma unroll
    for (int j = 0; j < 8; j++) {
        int idx = t + j * 256;
        int c  = idx >> 4;
        int p4 = idx & 15;
        float4 v = *(const float4*)(x + ((size_t)(b * C_ + c)) * HW_ + pxbase + p4 * 4);
        uint2 hi, lo; split4(v, hi, lo);
        uint32_t off = (uint32_t)(c * PALD_ + p4 * 4) * 2;
        *(uint2*)(sm + PSA_HI_ + off) = hi;
        *(uint2*)(sm + PSA_LO_ + off) = lo;
    }

    const int w = t >> 5, lane = t & 31;
    const int m0 = (w & 1) * 32;
    const int n0 = (w >> 1) * 32;
    const int lq = lane & 15;

    const uint32_t a_base = smb + PSA_HI_ +
        (uint32_t)(((lane & 7) + ((lane >> 4) & 1) * 8) * PALD_ +
                   (m0 + ((lane >> 3) & 1) * 8)) * 2;
    const uint32_t b_base = smb + PWA_ +
        (uint32_t)((n0 + (lq & 7)) * WLDH_) * 2 + ((lq >> 3) & 1) * 16;

#pragma unroll 1
    for (int mat = 0; mat < 3; mat++) {
        cp_wait_all();
        __syncthreads();               // W[mat] resident; A resident

        float acc[2][4][4];
#pragma unroll
        for (int mt = 0; mt < 2; mt++)
#pragma unroll
            for (int nt = 0; nt < 4; nt++)
#pragma unroll
                for (int e = 0; e < 4; e++) acc[mt][nt][e] = 0.f;

#pragma unroll
        for (int ks = 0; ks < 8; ks++) {
            uint32_t ahi[2][4], alo[2][4];
#pragma unroll
            for (int mt = 0; mt < 2; mt++) {
                uint32_t aa = a_base + (uint32_t)(ks * 16 * PALD_ * 2 + mt * 32);
                ldsm_x4_trans(ahi[mt], aa);
                ldsm_x4_trans(alo[mt], aa + (PSA_LO_ - PSA_HI_));
            }
#pragma unroll
            for (int nt = 0; nt < 4; nt++) {
                uint32_t ba = b_base + (uint32_t)(nt * 8 * WLDH_ * 2 + ks * 32);
                uint32_t bh0, bh1, bl0, bl1;
                ldsm_x2(bh0, bh1, ba);
                ldsm_x2(bl0, bl1, ba + WIMG_);
#pragma unroll
                for (int mt = 0; mt < 2; mt++) {
                    mma16816(acc[mt][nt], ahi[mt], bh0, bh1);
                    mma16816(acc[mt][nt], ahi[mt], bl0, bl1);
                    mma16816(acc[mt][nt], alo[mt], bh0, bh1);
                }
            }
        }

        // ---- epilogue ----
#pragma unroll
        for (int mt = 0; mt < 2; mt++) {
#pragma unroll
            for (int nt = 0; nt < 4; nt++) {
                int nn = n0 + nt * 8 + (lane & 3) * 2;
                int cc = nn >> 4, ch16 = nn & 15;
                int flat = pxbase + m0 + mt * 16 + (lane >> 2);
                float* dst = g_qkv + (size_t)mat * MAT_STRIDE_ +
                             (size_t)(b * NC_ + cc) * CHUNK_STRIDE_ +
                             (size_t)flat * 16 + ch16;
                *(float2*)dst          = make_float2(acc[mt][nt][0], acc[mt][nt][1]);
                *(float2*)(dst + 128)  = make_float2(acc[mt][nt][2], acc[mt][nt][3]);
            }
        }
        __syncthreads();               // all reads of W buffer done

        // issue next W image copy (single buffer reuse)
        if (mat < 2) {
            const char* src = (const char*)g_w16[mat + 1];
            uint32_t dst = smb + PWA_;
#pragma unroll
            for (int i = 0; i < 17; i++) {
                int idx = t + i * 256;
                if (idx < WPAIR_ / 16)
                    cp16(dst + idx * 16, src + idx * 16);
            }
            cp_commit();
        }
    }
}

// ---------------- Kernel 2: windowed attention (proven R5 design) ------------
#define TW_ 16
#define TH_ 8
#define KW_ (TW_ + KS_ - 1)        // 22
#define KH_ (TH_ + KS_ - 1)        // 14
#define NGR_ 4
#define PLANE_ (KH_ * KW_)          // 308
#define TILE_F4_ (4 * PLANE_)       // 1232
#define RED_STRIDE_ 65
#define SMEM_TILES_F4_ (NGR_ * 2 * TILE_F4_)
#define SMEM_BYTES_ (SMEM_TILES_F4_ * 16 + 128 * RED_STRIDE_ * 4 + 112 * 4)

__device__ __forceinline__ void cp_stage(float4* __restrict__ dst,
                                         const float* __restrict__ base,
                                         int y0, int x0, int pid)
{
#pragma unroll
    for (int it = 0; it < 10; it++) {
        int i = pid + it * 128;
        if (i < TILE_F4_) {
            int c4  = i / PLANE_;
            int rem = i - c4 * PLANE_;
            int yy  = rem / KW_;
            int xx  = rem - yy * KW_;
            int gy = y0 - PAD_ + yy, gx = x0 - PAD_ + xx;
            bool inb = ((unsigned)gy < H_) && ((unsigned)gx < W_);
            const float* src = base + ((size_t)(inb ? gy : 0) * W_ + (inb ? gx : 0)) * CC_ + c4 * 4;
            unsigned daddr = (unsigned)__cvta_generic_to_shared(dst + i);
            int sz = inb ? 16 : 0;
            asm volatile("cp.async.cg.shared.global [%0], [%1], 16, %2;"
                         :: "r"(daddr), "l"(src), "r"(sz));
        }
    }
}
__device__ __forceinline__ void group_bar(int g) {
    asm volatile("bar.sync %0, %1;" :: "r"(1 + g), "r"(128) : "memory");
}

__global__ void __launch_bounds__(512, 1) attn_kernel(
    const float* __restrict__ relx, const float* __restrict__ rely,
    float* __restrict__ out)
{
    extern __shared__ float4 sm4[];
    float* red  = (float*)(sm4 + SMEM_TILES_F4_);
    float* srel = red + 128 * RED_STRIDE_;

    const int t   = threadIdx.x;
    const int g   = t >> 7;
    const int pid = t & 127;
    const int tx  = pid & 15, ty = pid >> 4;
    const int b   = blockIdx.z;
    const int x0  = blockIdx.x * TW_, y0 = blockIdx.y * TH_;
    const int px  = x0 + tx, py = y0 + ty;

    if (t < 112) srel[t] = (t < 56) ? relx[t] : rely[t - 56];

    float4* tile = sm4 + g * (2 * TILE_F4_);
    const float* kb = g_qkv + MAT_STRIDE_;
    const float* vb = g_qkv + 2 * MAT_STRIDE_;

    cp_stage(tile,            kb + (size_t)(b * NC_ + 2 * g    ) * CHUNK_STRIDE_, y0, x0, pid);
    cp_stage(tile + TILE_F4_, kb + (size_t)(b * NC_ + 2 * g + 1) * CHUNK_STRIDE_, y0, x0, pid);
    cp_commit();
    cp_wait_all();
    group_bar(g);

    float logit[49];
#pragma unroll
    for (int i = 0; i < 49; i++) logit[i] = 0.f;
    float qxs[8], qys[8];
#pragma unroll
    for (int i = 0; i < 8; i++) { qxs[i] = 0.f; qys[i] = 0.f; }

#pragma unroll 1
    for (int s = 0; s < 2; s++) {
        const float4* tp = tile + s * TILE_F4_;
        const float4* qp = (const float4*)(g_qkv +
            (size_t)(b * NC_ + 2 * g + s) * CHUNK_STRIDE_ +
            ((size_t)py * W_ + px) * CC_);
        float4 q0 = qp[0], q1 = qp[1], q2 = qp[2], q3 = qp[3];

        qxs[0] += q0.x; qxs[1] += q0.y; qxs[2] += q0.z; qxs[3] += q0.w;
        qxs[4] += q1.x; qxs[5] += q1.y; qxs[6] += q1.z; qxs[7] += q1.w;
        qys[0] += q2.x; qys[1] += q2.y; qys[2] += q2.z; qys[3] += q2.w;
        qys[4] += q3.x; qys[5] += q3.y; qys[6] += q3.z; qys[7] += q3.w;

#pragma unroll
        for (int ki = 0; ki < KS_; ki++) {
#pragma unroll
            for (int kj = 0; kj < KS_; kj++) {
                int o = (ty + ki) * KW_ + tx + kj;
                float4 k0 = tp[0 * PLANE_ + o];
                float4 k1 = tp[1 * PLANE_ + o];
                float4 k2 = tp[2 * PLANE_ + o];
                float4 k3 = tp[3 * PLANE_ + o];
                float sacc = logit[ki * KS_ + kj];
                sacc = fmaf(q0.x, k0.x, sacc); sacc = fmaf(q0.y, k0.y, sacc);
                sacc = fmaf(q0.z, k0.z, sacc); sacc = fmaf(q0.w, k0.w, sacc);
                sacc = fmaf(q1.x, k1.x, sacc); sacc = fmaf(q1.y, k1.y, sacc);
                sacc = fmaf(q1.z, k1.z, sacc); sacc = fmaf(q1.w, k1.w, sacc);
                sacc = fmaf(q2.x, k2.x, sacc); sacc = fmaf(q2.y, k2.y, sacc);
                sacc = fmaf(q2.z, k2.z, sacc); sacc = fmaf(q2.w, k2.w, sacc);
                sacc = fmaf(q3.x, k3.x, sacc); sacc = fmaf(q3.y, k3.y, sacc);
                sacc = fmaf(q3.z, k3.z, sacc); sacc = fmaf(q3.w, k3.w, sacc);
                logit[ki * KS_ + kj] = sacc;
            }
        }
    }

    group_bar(g);
    cp_stage(tile,            vb + (size_t)(b * NC_ + 2 * g    ) * CHUNK_STRIDE_, y0, x0, pid);
    cp_stage(tile + TILE_F4_, vb + (size_t)(b * NC_ + 2 * g + 1) * CHUNK_STRIDE_, y0, x0, pid);
    cp_commit();

    float* rp = red + pid * RED_STRIDE_;
    __syncthreads();
    if (g == 0) {
#pragma unroll
        for (int j = 0; j < 49; j++) rp[j] = logit[j];
#pragma unroll
        for (int j = 0; j < 8; j++) { rp[49 + j] = qxs[j]; rp[57 + j] = qys[j]; }
    }
    __syncthreads();
    if (g == 1) {
#pragma unroll
        for (int j = 0; j < 49; j++) rp[j] += logit[j];
#pragma unroll
        for (int j = 0; j < 8; j++) { rp[49 + j] += qxs[j]; rp[57 + j] += qys[j]; }
    }
    __syncthreads();
    if (g == 2) {
#pragma unroll
        for (int j = 0; j < 49; j++) rp[j] += logit[j];
#pragma unroll
        for (int j = 0; j < 8; j++) { rp[49 + j] += qxs[j]; rp[57 + j] += qys[j]; }
    }
    __syncthreads();
    if (g == 3) {
#pragma unroll
        for (int j = 0; j < 49; j++) rp[j] += logit[j];
#pragma unroll
        for (int j = 0; j < 8; j++) { rp[49 + j] += qxs[j]; rp[57 + j] += qys[j]; }
    }
    __syncthreads();
#pragma unroll
    for (int j = 0; j < 49; j++) logit[j] = rp[j];
#pragma unroll
    for (int j = 0; j < 8; j++) { qxs[j] = rp[49 + j]; qys[j] = rp[57 + j]; }

    float bxv[7], byv[7];
#pragma unroll
    for (int kj = 0; kj < 7; kj++) {
        float s = 0.f;
#pragma unroll
        for (int xi = 0; xi < 8; xi++) s = fmaf(qxs[xi], srel[xi * 7 + kj], s);
        bxv[kj] = s;
    }
#pragma unroll
    for (int ki = 0; ki < 7; ki++) {
        float s = 0.f;
#pragma unroll
        for (int yi = 0; yi < 8; yi++) s = fmaf(qys[yi], srel[56 + yi * 7 + ki], s);
        byv[ki] = s;
    }
    float m = -1e30f;
#pragma unroll
    for (int ki = 0; ki < 7; ki++)
#pragma unroll
        for (int kj = 0; kj < 7; kj++) {
            float l = logit[ki * 7 + kj] + bxv[kj] + byv[ki];
            logit[ki * 7 + kj] = l;
            m = fmaxf(m, l);
        }
    float ssum = 0.f;
#pragma unroll
    for (int i = 0; i < 49; i++) {
        float e = __expf(logit[i] - m);
        logit[i] = e;
        ssum += e;
    }
    float inv = 1.f / ssum;
#pragma unroll
    for (int i = 0; i < 49; i++) logit[i] *= inv;

    cp_wait_all();
    group_bar(g);

#pragma unroll 1
    for (int s = 0; s < 2; s++) {
        const float4* tp = tile + s * TILE_F4_;
        float4 o0 = make_float4(0.f, 0.f, 0.f, 0.f), o1 = o0, o2 = o0, o3 = o0;
#pragma unroll
        for (int ki = 0; ki < KS_; ki++) {
#pragma unroll
            for (int kj = 0; kj < KS_; kj++) {
                float a = logit[ki * KS_ + kj];
                int o = (ty + ki) * KW_ + tx + kj;
                float4 v0 = tp[0 * PLANE_ + o];
                float4 v1 = tp[1 * PLANE_ + o];
                float4 v2 = tp[2 * PLANE_ + o];
                float4 v3 = tp[3 * PLANE_ + o];
                o0.x = fmaf(a, v0.x, o0.x); o0.y = fmaf(a, v0.y, o0.y);
                o0.z = fmaf(a, v0.z, o0.z); o0.w = fmaf(a, v0.w, o0.w);
                o1.x = fmaf(a, v1.x, o1.x); o1.y = fmaf(a, v1.y, o1.y);
                o1.z = fmaf(a, v1.z, o1.z); o1.w = fmaf(a, v1.w, o1.w);
                o2.x = fmaf(a, v2.x, o2.x); o2.y = fmaf(a, v2.y, o2.y);
                o2.z = fmaf(a, v2.z, o2.z); o2.w = fmaf(a, v2.w, o2.w);
                o3.x = fmaf(a, v3.x, o3.x); o3.y = fmaf(a, v3.y, o3.y);
                o3.z = fmaf(a, v3.z, o3.z); o3.w = fmaf(a, v3.w, o3.w);
            }
        }
        int c = 2 * g + s;
        size_t ob = ((size_t)(b * C_ + c * CC_) * H_ + py) * W_ + px;
        out[ob +  0 * HW_] = o0.x; out[ob +  1 * HW_] = o0.y;
        out[ob +  2 * HW_] = o0.z; out[ob +  3 * HW_] = o0.w;
        out[ob +  4 * HW_] = o1.x; out[ob +  5 * HW_] = o1.y;
        out[ob +  6 * HW_] = o1.z; out[ob +  7 * HW_] = o1.w;
        out[ob +  8 * HW_] = o2.x; out[ob +  9 * HW_] = o2.y;
        out[ob + 10 * HW_] = o2.z; out[ob + 11 * HW_] = o2.w;
        out[ob + 12 * HW_] = o3.x; out[ob + 13 * HW_] = o3.y;
        out[ob + 14 * HW_] = o3.z; out[ob + 15 * HW_] = o3.w;
    }
}

// ---------------- launch -----------------------------------------------------
extern "C" void kernel_launch(void* const* d_in, const int* in_sizes, int n_in,
                              void* d_out, int out_size)
{
    const float* x    = (const float*)d_in[0];
    const float* wq   = (const float*)d_in[1];
    const float* wk   = (const float*)d_in[2];
    const float* wv   = (const float*)d_in[3];
    const float* relx = (const float*)d_in[4];
    const float* rely = (const float*)d_in[5];
    float* out = (float*)d_out;

    cudaFuncSetAttribute(proj_mma_kernel,
                         cudaFuncAttributeMaxDynamicSharedMemorySize, PSM_BYTES_);
    cudaFuncSetAttribute(attn_kernel,
                         cudaFuncAttributeMaxDynamicSharedMemorySize, SMEM_BYTES_);

    wprep_kernel<<<dim3(3, 16), 256>>>(wq, wk, wv);
    proj_mma_kernel<<<dim3(64, B_), 256, PSM_BYTES_>>>(x);
    attn_kernel<<<dim3(W_ / TW_, H_ / TH_, B_), 512, SMEM_BYTES_>>>(relx, rely, out);
}

// round 16
// speedup vs baseline: 1.1442x; 1.0537x over previous
#include <cuda_runtime.h>
#include <cuda_bf16.h>
#include <cstdint>

#define B_   4
#define C_   128
#define H_   64
#define W_   64
#define KS_  7
#define PAD_ 3
#define HW_  (H_*W_)

// bf16 hi/lo images produced by proj:
//   q: [b][ch][px]   (ch-major planes, for Q tile row loads)
//   k,v: [b][px][ch] (pixel-major, 256B per pixel per image)
__device__ __align__(16) unsigned short g_qh[(size_t)B_*C_*HW_];
__device__ __align__(16) unsigned short g_ql[(size_t)B_*C_*HW_];
__device__ __align__(16) unsigned short g_kh[(size_t)B_*HW_*C_];
__device__ __align__(16) unsigned short g_kl[(size_t)B_*HW_*C_];
__device__ __align__(16) unsigned short g_vh[(size_t)B_*HW_*C_];
__device__ __align__(16) unsigned short g_vl[(size_t)B_*HW_*C_];

// Pre-split bf16 W images in the padded [n][136] SMEM layout: [mat][hi/lo]
#define WLDH_ 136
__device__ __align__(16) unsigned short g_w16[3][2][128 * WLDH_];

// ================= common helpers =================
__device__ __forceinline__ uint32_t smem_u32(const void* p) {
    uint32_t a;
    asm("{ .reg .u64 t; cvta.to.shared.u64 t, %1; cvt.u32.u64 %0, t; }"
        : "=r"(a) : "l"(p));
    return a;
}
__device__ __forceinline__ void ldsm_x4_trans(uint32_t* r, uint32_t addr) {
    asm volatile("ldmatrix.sync.aligned.m8n8.x4.trans.shared.b16 {%0,%1,%2,%3}, [%4];"
                 : "=r"(r[0]), "=r"(r[1]), "=r"(r[2]), "=r"(r[3]) : "r"(addr));
}
__device__ __forceinline__ void ldsm_x2(uint32_t& b0, uint32_t& b1, uint32_t addr) {
    asm volatile("ldmatrix.sync.aligned.m8n8.x2.shared.b16 {%0,%1}, [%2];"
                 : "=r"(b0), "=r"(b1) : "r"(addr));
}
__device__ __forceinline__ void mma16816(float* d, const uint32_t* a,
                                         uint32_t b0, uint32_t b1) {
    asm volatile(
        "mma.sync.aligned.m16n8k16.row.col.f32.bf16.bf16.f32 "
        "{%0,%1,%2,%3}, {%4,%5,%6,%7}, {%8,%9}, {%0,%1,%2,%3};"
        : "+f"(d[0]), "+f"(d[1]), "+f"(d[2]), "+f"(d[3])
        : "r"(a[0]), "r"(a[1]), "r"(a[2]), "r"(a[3]), "r"(b0), "r"(b1));
}
__device__ __forceinline__ void split1(float a, unsigned short& h, unsigned short& l) {
    __nv_bfloat16 hb = __float2bfloat16(a);
    __nv_bfloat16 lb = __float2bfloat16(a - __bfloat162float(hb));
    h = __bfloat16_as_ushort(hb);
    l = __bfloat16_as_ushort(lb);
}
__device__ __forceinline__ void split4(float4 v, uint2& hi, uint2& lo) {
    unsigned short h[4], l[4];
    split1(v.x, h[0], l[0]); split1(v.y, h[1], l[1]);
    split1(v.z, h[2], l[2]); split1(v.w, h[3], l[3]);
    hi = make_uint2((uint32_t)h[0] | ((uint32_t)h[1] << 16),
                    (uint32_t)h[2] | ((uint32_t)h[3] << 16));
    lo = make_uint2((uint32_t)l[0] | ((uint32_t)l[1] << 16),
                    (uint32_t)l[2] | ((uint32_t)l[3] << 16));
}
__device__ __forceinline__ void cp_commit() {
    asm volatile("cp.async.commit_group;" ::: "memory");
}
__device__ __forceinline__ void cp_wait_all() {
    asm volatile("cp.async.wait_all;" ::: "memory");
}
__device__ __forceinline__ void cp16(uint32_t daddr, const void* src) {
    asm volatile("cp.async.cg.shared.global [%0], [%1], 16;"
                 :: "r"(daddr), "l"(src));
}
__device__ __forceinline__ void cp16z(uint32_t daddr, const void* src, int sz) {
    asm volatile("cp.async.cg.shared.global [%0], [%1], 16, %2;"
                 :: "r"(daddr), "l"(src), "r"(sz));
}

// ---------------- Kernel 0: parallel W -> split-bf16 padded images -----------
__global__ __launch_bounds__(256) void wprep_kernel(
    const float* __restrict__ wq, const float* __restrict__ wk,
    const float* __restrict__ wv)
{
    const int mat = blockIdx.x, seg = blockIdx.y;
    const float* w = (mat == 0) ? wq : (mat == 1) ? wk : wv;
    const int t = threadIdx.x;
    int n  = seg * 8 + (t >> 5);
    int k4 = t & 31;
    float4 v = *(const float4*)(w + n * 128 + k4 * 4);
    uint2 hi, lo; split4(v, hi, lo);
    uint32_t off = (uint32_t)(n * WLDH_ + k4 * 4);
    *(uint2*)&g_w16[mat][0][off] = hi;
    *(uint2*)&g_w16[mat][1][off] = lo;
}

// ---------------- Kernel 1: QKV projection (proven MMA core), bf16 epilogue --
#define PALD_ 72
#define PSA_HI_ 0
#define PSA_LO_ (PSA_HI_ + 128 * PALD_ * 2)    // 18432
#define PWA_    (PSA_LO_ + 128 * PALD_ * 2)    // 36864
#define WIMG_   (128 * WLDH_ * 2)              // 34816
#define WPAIR_  (2 * WIMG_)                    // 69632
#define PSM_BYTES_ (PWA_ + WPAIR_)             // 106496 -> 2 CTAs/SM

__global__ void __launch_bounds__(256, 2) proj_mma_kernel(const float* __restrict__ x)
{
    extern __shared__ char sm[];
    const uint32_t smb = smem_u32(sm);
    const int t = threadIdx.x;
    const int pxbase = blockIdx.x * 64;
    const int b = blockIdx.y;

    // prologue: W0 image copy (overlapped by X conversion)
    {
        const char* src = (const char*)g_w16[0];
        uint32_t dst = smb + PWA_;
#pragma unroll
        for (int i = 0; i < 17; i++) {
            int idx = t + i * 256;
            if (idx < WPAIR_ / 16) cp16(dst + idx * 16, src + idx * 16);
        }
        cp_commit();
    }

    // X tile: [128ch][64px] -> split bf16 [ch][px]
#pragma unroll
    for (int j = 0; j < 8; j++) {
        int idx = t + j * 256;
        int c  = idx >> 4;
        int p4 = idx & 15;
        float4 v = *(const float4*)(x + ((size_t)(b * C_ + c)) * HW_ + pxbase + p4 * 4);
        uint2 hi, lo; split4(v, hi, lo);
        uint32_t off = (uint32_t)(c * PALD_ + p4 * 4) * 2;
        *(uint2*)(sm + PSA_HI_ + off) = hi;
        *(uint2*)(sm + PSA_LO_ + off) = lo;
    }

    const int w = t >> 5, lane = t & 31;
    const int m0 = (w & 1) * 32;
    const int n0 = (w >> 1) * 32;
    const int lq = lane & 15;

    const uint32_t a_base = smb + PSA_HI_ +
        (uint32_t)(((lane & 7) + ((lane >> 4) & 1) * 8) * PALD_ +
                   (m0 + ((lane >> 3) & 1) * 8)) * 2;
    const uint32_t b_base = smb + PWA_ +
        (uint32_t)((n0 + (lq & 7)) * WLDH_) * 2 + ((lq >> 3) & 1) * 16;

#pragma unroll 1
    for (int mat = 0; mat < 3; mat++) {
        cp_wait_all();
        __syncthreads();

        float acc[2][4][4];
#pragma unroll
        for (int mt = 0; mt < 2; mt++)
#pragma unroll
            for (int nt = 0; nt < 4; nt++)
#pragma unroll
                for (int e = 0; e < 4; e++) acc[mt][nt][e] = 0.f;

#pragma unroll
        for (int ks = 0; ks < 8; ks++) {
            uint32_t ahi[2][4], alo[2][4];
#pragma unroll
            for (int mt = 0; mt < 2; mt++) {
                uint32_t aa = a_base + (uint32_t)(ks * 16 * PALD_ * 2 + mt * 32);
                ldsm_x4_trans(ahi[mt], aa);
                ldsm_x4_trans(alo[mt], aa + (PSA_LO_ - PSA_HI_));
            }
#pragma unroll
            for (int nt = 0; nt < 4; nt++) {
                uint32_t ba = b_base + (uint32_t)(nt * 8 * WLDH_ * 2 + ks * 32);
                uint32_t bh0, bh1, bl0, bl1;
                ldsm_x2(bh0, bh1, ba);
                ldsm_x2(bl0, bl1, ba + WIMG_);
#pragma unroll
                for (int mt = 0; mt < 2; mt++) {
                    mma16816(acc[mt][nt], ahi[mt], bh0, bh1);
                    mma16816(acc[mt][nt], ahi[mt], bl0, bl1);
                    mma16816(acc[mt][nt], alo[mt], bh0, bh1);
                }
            }
        }

        // epilogue: write split-bf16 images
#pragma unroll
        for (int mt = 0; mt < 2; mt++) {
#pragma unroll
            for (int nt = 0; nt < 4; nt++) {
                int nn = n0 + nt * 8 + (lane & 3) * 2;       // even ch
                int f0 = pxbase + m0 + mt * 16 + (lane >> 2);
                int f1 = f0 + 8;
                unsigned short h0,l0,h1,l1,h2,l2,h3,l3;
                split1(acc[mt][nt][0], h0, l0);
                split1(acc[mt][nt][1], h1, l1);
                split1(acc[mt][nt][2], h2, l2);
                split1(acc[mt][nt][3], h3, l3);
                if (mat == 0) {
                    size_t c0 = ((size_t)(b * C_ + nn)) * HW_;
                    size_t c1 = c0 + HW_;
                    g_qh[c0 + f0] = h0; g_qh[c1 + f0] = h1;
                    g_qh[c0 + f1] = h2; g_qh[c1 + f1] = h3;
                    g_ql[c0 + f0] = l0; g_ql[c1 + f0] = l1;
                    g_ql[c0 + f1] = l2; g_ql[c1 + f1] = l3;
                } else {
                    unsigned short* ih = (mat == 1) ? g_kh : g_vh;
                    unsigned short* il = (mat == 1) ? g_kl : g_vl;
                    size_t p0 = ((size_t)(b * HW_) + f0) * C_ + nn;
                    size_t p1 = ((size_t)(b * HW_) + f1) * C_ + nn;
                    *(ushort2*)&ih[p0] = make_ushort2(h0, h1);
                    *(ushort2*)&il[p0] = make_ushort2(l0, l1);
                    *(ushort2*)&ih[p1] = make_ushort2(h2, h3);
                    *(ushort2*)&il[p1] = make_ushort2(l2, l3);
                }
            }
        }
        __syncthreads();

        if (mat < 2) {
            const char* src = (const char*)g_w16[mat + 1];
            uint32_t dst = smb + PWA_;
#pragma unroll
            for (int i = 0; i < 17; i++) {
                int idx = t + i * 256;
                if (idx < WPAIR_ / 16) cp16(dst + idx * 16, src + idx * 16);
            }
            cp_commit();
        }
    }
}

// ---------------- Kernel 2: HMMA windowed attention --------------------------
// 8x8 px tiles, grid (8,8,4), 256 threads = 8 warps.
// QK: logits[64px, 208] = Q[64,128] . K[208,128]^T  (3-term bf16 split)
// AV: out_t[128ch, 64px] = V_t . W^T                (3-term bf16 split)
#define NBR_ 196
#define NBK_ 208            // padded (13 ksteps of 16 / 26 ntiles of 8)
#define LP_  208            // logits pitch (floats)
#define WP_  216            // weights pitch (halfs); 432 B rows
// SMEM map (bytes)
#define SQ_HI2_ 0
#define SQ_LO2_ 18432                        // 128 x 72 halfs
#define SB2_    36864                        // K/V region
#define SBIMG2_ (NBK_ * 72 * 2)              // 29952 per image per half
#define SBHALF2_ (2 * SBIMG2_)               // 59904 per ch-half (hi+lo)
#define SC2_    (SB2_ + 2 * SBHALF2_)        // 156672: logits / weights (reused)
#define SWH2_   SC2_
#define SWL2_   (SC2_ + 64 * WP_ * 2)        // +27648
#define SREL2_  (SC2_ + 56320)               // 212992
#define ASM_BYTES_ (SREL2_ + 448)            // 213440

__global__ void __launch_bounds__(256, 1) attn_kernel(
    const float* __restrict__ relx, const float* __restrict__ rely,
    float* __restrict__ out)
{
    extern __shared__ char sm[];
    const uint32_t smb = smem_u32(sm);
    const int t = threadIdx.x;
    const int w = t >> 5, lane = t & 31;
    const int lq = lane & 15;
    const int b  = blockIdx.z;
    const int x0 = blockIdx.x * 8, y0 = blockIdx.y * 8;
    float* srel = (float*)(sm + SREL2_);

    if (t < 112) srel[t] = (t < 56) ? relx[t] : rely[t - 56];

    // ---- load Q tile [ch 128][px 64] hi/lo ----
#pragma unroll
    for (int img = 0; img < 2; img++) {
        const unsigned short* src = img ? g_ql : g_qh;
        uint32_t dbase = smb + (img ? SQ_LO2_ : SQ_HI2_);
#pragma unroll
        for (int i0 = 0; i0 < 4; i0++) {
            int i = t + i0 * 256;            // 1024 = 128ch x 8 rows
            int ch = i >> 3, yy = i & 7;
            cp16(dbase + (uint32_t)(ch * 144 + yy * 16),
                 src + ((size_t)(b * C_ + ch)) * HW_ + (size_t)(y0 + yy) * W_ + x0);
        }
    }
    // ---- load K: 208 nbr rows x 128 ch, split in 2 ch-halves; halo zero-fill
#pragma unroll
    for (int half = 0; half < 2; half++) {
#pragma unroll
        for (int img = 0; img < 2; img++) {
            const unsigned short* src0 = img ? g_kl : g_kh;
            uint32_t dbase = smb + SB2_ + half * SBHALF2_ + img * SBIMG2_;
            for (int i = t; i < NBK_ * 8; i += 256) {
                int r = i >> 3, c8 = i & 7;
                int yy = r / 14, xx = r - yy * 14;
                int gy = y0 - PAD_ + yy, gx = x0 - PAD_ + xx;
                bool inb = (r < NBR_) && ((unsigned)gy < H_) && ((unsigned)gx < W_);
                const unsigned short* s = src0 +
                    ((size_t)(b * HW_ + (inb ? gy : 0) * W_ + (inb ? gx : 0))) * C_ +
                    half * 64 + c8 * 8;
                cp16z(dbase + (uint32_t)(r * 144 + c8 * 16), s, inb ? 16 : 0);
            }
        }
    }
    cp_commit();
    cp_wait_all();
    __syncthreads();

    // ---- QK MMA: warp -> m-tile (w&3), n-tiles [(w>>2)*13, +13) ----
    const int mq = (w & 3) * 16;
    const int nbase = (w >> 2) * 13;
    const uint32_t aq_base = smb + SQ_HI2_ +
        (uint32_t)(((lane & 7) + ((lane >> 4) & 1) * 8) * 72 +
                   (mq + ((lane >> 3) & 1) * 8)) * 2;
    const uint32_t bK_off = (uint32_t)((lq & 7) * 144 + ((lq >> 3) & 1) * 16);

    float acc[13][4];
#pragma unroll
    for (int j = 0; j < 13; j++)
#pragma unroll
        for (int e = 0; e < 4; e++) acc[j][e] = 0.f;

#pragma unroll
    for (int half = 0; half < 2; half++) {
        const uint32_t kbase = smb + SB2_ + half * SBHALF2_;
#pragma unroll
        for (int ks = 0; ks < 4; ks++) {
            int ch0 = half * 64 + ks * 16;
            uint32_t aa = aq_base + (uint32_t)(ch0 * 144);
            uint32_t ahi[4], alo[4];
            ldsm_x4_trans(ahi, aa);
            ldsm_x4_trans(alo, aa + 18432);
#pragma unroll
            for (int j = 0; j < 13; j++) {
                uint32_t ba = kbase + bK_off + (uint32_t)((nbase + j) * 8 * 144 + ks * 32);
                uint32_t bh0, bh1, bl0, bl1;
                ldsm_x2(bh0, bh1, ba);
                ldsm_x2(bl0, bl1, ba + SBIMG2_);
                mma16816(acc[j], ahi, bh0, bh1);
                mma16816(acc[j], ahi, bl0, bl1);
                mma16816(acc[j], alo, bh0, bh1);
            }
        }
    }

    // ---- store logits [64][208] ----
    {
        float* lg = (float*)(sm + SC2_);
        int r0 = mq + (lane >> 2);
#pragma unroll
        for (int j = 0; j < 13; j++) {
            int col = (nbase + j) * 8 + (lane & 3) * 2;
            *(float2*)&lg[(size_t)r0 * LP_ + col]       = make_float2(acc[j][0], acc[j][1]);
            *(float2*)&lg[(size_t)(r0 + 8) * LP_ + col] = make_float2(acc[j][2], acc[j][3]);
        }
    }
    __syncthreads();   // logits visible; K region fully consumed

    // ---- issue V loads into the K region (overlaps softmax) ----
#pragma unroll
    for (int half = 0; half < 2; half++) {
#pragma unroll
        for (int img = 0; img < 2; img++) {
            const unsigned short* src0 = img ? g_vl : g_vh;
            uint32_t dbase = smb + SB2_ + half * SBHALF2_ + img * SBIMG2_;
            for (int i = t; i < NBK_ * 8; i += 256) {
                int r = i >> 3, c8 = i & 7;
                int yy = r / 14, xx = r - yy * 14;
                int gy = y0 - PAD_ + yy, gx = x0 - PAD_ + xx;
                bool inb = (r < NBR_) && ((unsigned)gy < H_) && ((unsigned)gx < W_);
                const unsigned short* s = src0 +
                    ((size_t)(b * HW_ + (inb ? gy : 0) * W_ + (inb ? gx : 0))) * C_ +
                    half * 64 + c8 * 8;
                cp16z(dbase + (uint32_t)(r * 144 + c8 * 16), s, inb ? 16 : 0);
            }
        }
    }
    cp_commit();

    // ---- softmax + bias (threads 0..63, one pixel each) ----
    float w49[49];
    if (t < 64) {
        const int p = t, ty = p >> 3, tx = p & 7;
        const float* lg = (const float*)(sm + SC2_);
#pragma unroll
        for (int ki = 0; ki < 7; ki++)
#pragma unroll
            for (int kj = 0; kj < 7; kj++)
                w49[ki * 7 + kj] = lg[(size_t)p * LP_ + (ty + ki) * 14 + tx + kj];

        // q channel-group sums from Q SMEM (hi+lo)
        float qs[16];
#pragma unroll
        for (int i = 0; i < 16; i++) qs[i] = 0.f;
#pragma unroll 4
        for (int ch = 0; ch < 128; ch++) {
            uint32_t off = (uint32_t)(ch * 144 + p * 2);
            unsigned short h = *(unsigned short*)(sm + SQ_HI2_ + off);
            unsigned short l = *(unsigned short*)(sm + SQ_LO2_ + off);
            float qv = __bfloat162float(__ushort_as_bfloat16(h)) +
                       __bfloat162float(__ushort_as_bfloat16(l));
            qs[ch & 15] += qv;
        }
        float bx[7], by[7];
#pragma unroll
        for (int kj = 0; kj < 7; kj++) {
            float s = 0.f;
#pragma unroll
            for (int xi = 0; xi < 8; xi++) s = fmaf(qs[xi], srel[xi * 7 + kj], s);
            bx[kj] = s;
        }
#pragma unroll
        for (int ki = 0; ki < 7; ki++) {
            float s = 0.f;
#pragma unroll
            for (int yi = 0; yi < 8; yi++) s = fmaf(qs[8 + yi], srel[56 + yi * 7 + ki], s);
            by[ki] = s;
        }
        float m = -1e30f;
#pragma unroll
        for (int ki = 0; ki < 7; ki++)
#pragma unroll
            for (int kj = 0; kj < 7; kj++) {
                float v = w49[ki * 7 + kj] + bx[kj] + by[ki];
                w49[ki * 7 + kj] = v;
                m = fmaxf(m, v);
            }
        float ssum = 0.f;
#pragma unroll
        for (int i = 0; i < 49; i++) { float e = __expf(w49[i] - m); w49[i] = e; ssum += e; }
        float inv = 1.f / ssum;
#pragma unroll
        for (int i = 0; i < 49; i++) w49[i] *= inv;
    }
    __syncthreads();   // all logits reads done -> region reusable as weights

    // ---- write weights matrix [px 64][nbr 216] hi/lo (zero + scatter) ----
    if (t < 64) {
        const int p = t, ty = p >> 3, tx = p & 7;
#pragma unroll
        for (int i = 0; i < 27; i++) {
            *(uint4*)(sm + SWH2_ + p * 432 + i * 16) = make_uint4(0, 0, 0, 0);
            *(uint4*)(sm + SWL2_ + p * 432 + i * 16) = make_uint4(0, 0, 0, 0);
        }
#pragma unroll
        for (int ki = 0; ki < 7; ki++)
#pragma unroll
            for (int kj = 0; kj < 7; kj++) {
                int nbr = (ty + ki) * 14 + tx + kj;
                unsigned short h, l;
                split1(w49[ki * 7 + kj], h, l);
                *(unsigned short*)(sm + SWH2_ + p * 432 + nbr * 2) = h;
                *(unsigned short*)(sm + SWL2_ + p * 432 + nbr * 2) = l;
            }
    }
    cp_wait_all();
    __syncthreads();   // weights + V resident

    // ---- AV MMA (transposed): out_t[ch,px]; warp -> ch m-tile w ----
    {
        const int half = w >> 2;
        const int mch  = (w & 3) * 16;       // ch within half
        const uint32_t av_base = smb + SB2_ + half * SBHALF2_ +
            (uint32_t)(((lane & 7) + ((lane >> 4) & 1) * 8) * 144 +
                       (mch + ((lane >> 3) & 1) * 8) * 2);
        const uint32_t bw_off = (uint32_t)((lq & 7) * 432 + ((lq >> 3) & 1) * 16);

        float oacc[8][4];
#pragma unroll
        for (int j = 0; j < 8; j++)
#pragma unroll
            for (int e = 0; e < 4; e++) oacc[j][e] = 0.f;

#pragma unroll
        for (int ks = 0; ks < 13; ks++) {
            uint32_t aa = av_base + (uint32_t)(ks * 16 * 144);
            uint32_t vhi[4], vlo[4];
            ldsm_x4_trans(vhi, aa);
            ldsm_x4_trans(vlo, aa + SBIMG2_);
#pragma unroll
            for (int j = 0; j < 8; j++) {
                uint32_t ba = smb + SWH2_ + bw_off + (uint32_t)(j * 8 * 432 + ks * 32);
                uint32_t wh0, wh1, wl0, wl1;
                ldsm_x2(wh0, wh1, ba);
                ldsm_x2(wl0, wl1, ba + (SWL2_ - SWH2_));
                mma16816(oacc[j], vhi, wh0, wh1);
                mma16816(oacc[j], vhi, wl0, wl1);
                mma16816(oacc[j], vlo, wh0, wh1);
            }
        }

        // ---- write out BCHW: row = ch, col = px (y=j, x=(lane&3)*2) ----
        int ch0 = w * 16 + (lane >> 2);
#pragma unroll
        for (int j = 0; j < 8; j++) {
            int y = y0 + j;
            int xx = x0 + (lane & 3) * 2;
            size_t o0 = ((size_t)(b * C_ + ch0) * H_ + y) * W_ + xx;
            size_t o1 = ((size_t)(b * C_ + ch0 + 8) * H_ + y) * W_ + xx;
            *(float2*)&out[o0] = make_float2(oacc[j][0], oacc[j][1]);
            *(float2*)&out[o1] = make_float2(oacc[j][2], oacc[j][3]);
        }
    }
}

// ---------------- launch -----------------------------------------------------
extern "C" void kernel_launch(void* const* d_in, const int* in_sizes, int n_in,
                              void* d_out, int out_size)
{
    const float* x    = (const float*)d_in[0];
    const float* wq   = (const float*)d_in[1];
    const float* wk   = (const float*)d_in[2];
    const float* wv   = (const float*)d_in[3];
    const float* relx = (const float*)d_in[4];
    const float* rely = (const float*)d_in[5];
    float* out = (float*)d_out;

    cudaFuncSetAttribute(proj_mma_kernel,
                         cudaFuncAttributeMaxDynamicSharedMemorySize, PSM_BYTES_);
    cudaFuncSetAttribute(attn_kernel,
                         cudaFuncAttributeMaxDynamicSharedMemorySize, ASM_BYTES_);

    wprep_kernel<<<dim3(3, 16), 256>>>(wq, wk, wv);
    proj_mma_kernel<<<dim3(64, B_), 256, PSM_BYTES_>>>(x);
    attn_kernel<<<dim3(W_ / 8, H_ / 8, B_), 256, ASM_BYTES_>>>(relx, rely, out);
}

// round 17
// speedup vs baseline: 1.3116x; 1.1463x over previous
#include <cuda_runtime.h>
#include <cuda_bf16.h>
#include <cstdint>

#define B_   4
#define C_   128
#define H_   64
#define W_   64
#define KS_  7
#define PAD_ 3
#define HW_  (H_*W_)

// bf16 hi/lo images produced by proj, ALL pixel-major: [b][px][ch]
__device__ __align__(16) unsigned short g_qh[(size_t)B_*HW_*C_];
__device__ __align__(16) unsigned short g_ql[(size_t)B_*HW_*C_];
__device__ __align__(16) unsigned short g_kh[(size_t)B_*HW_*C_];
__device__ __align__(16) unsigned short g_kl[(size_t)B_*HW_*C_];
__device__ __align__(16) unsigned short g_vh[(size_t)B_*HW_*C_];
__device__ __align__(16) unsigned short g_vl[(size_t)B_*HW_*C_];

// Pre-split bf16 W images in the padded [n][136] SMEM layout: [mat][hi/lo]
#define WLDH_ 136
__device__ __align__(16) unsigned short g_w16[3][2][128 * WLDH_];

// ================= common helpers =================
__device__ __forceinline__ uint32_t smem_u32(const void* p) {
    uint32_t a;
    asm("{ .reg .u64 t; cvta.to.shared.u64 t, %1; cvt.u32.u64 %0, t; }"
        : "=r"(a) : "l"(p));
    return a;
}
__device__ __forceinline__ void ldsm_x4(uint32_t* r, uint32_t addr) {
    asm volatile("ldmatrix.sync.aligned.m8n8.x4.shared.b16 {%0,%1,%2,%3}, [%4];"
                 : "=r"(r[0]), "=r"(r[1]), "=r"(r[2]), "=r"(r[3]) : "r"(addr));
}
__device__ __forceinline__ void ldsm_x4_trans(uint32_t* r, uint32_t addr) {
    asm volatile("ldmatrix.sync.aligned.m8n8.x4.trans.shared.b16 {%0,%1,%2,%3}, [%4];"
                 : "=r"(r[0]), "=r"(r[1]), "=r"(r[2]), "=r"(r[3]) : "r"(addr));
}
__device__ __forceinline__ void ldsm_x2(uint32_t& b0, uint32_t& b1, uint32_t addr) {
    asm volatile("ldmatrix.sync.aligned.m8n8.x2.shared.b16 {%0,%1}, [%2];"
                 : "=r"(b0), "=r"(b1) : "r"(addr));
}
__device__ __forceinline__ void mma16816(float* d, const uint32_t* a,
                                         uint32_t b0, uint32_t b1) {
    asm volatile(
        "mma.sync.aligned.m16n8k16.row.col.f32.bf16.bf16.f32 "
        "{%0,%1,%2,%3}, {%4,%5,%6,%7}, {%8,%9}, {%0,%1,%2,%3};"
        : "+f"(d[0]), "+f"(d[1]), "+f"(d[2]), "+f"(d[3])
        : "r"(a[0]), "r"(a[1]), "r"(a[2]), "r"(a[3]), "r"(b0), "r"(b1));
}
__device__ __forceinline__ void split1(float a, unsigned short& h, unsigned short& l) {
    __nv_bfloat16 hb = __float2bfloat16(a);
    __nv_bfloat16 lb = __float2bfloat16(a - __bfloat162float(hb));
    h = __bfloat16_as_ushort(hb);
    l = __bfloat16_as_ushort(lb);
}
__device__ __forceinline__ void split4(float4 v, uint2& hi, uint2& lo) {
    unsigned short h[4], l[4];
    split1(v.x, h[0], l[0]); split1(v.y, h[1], l[1]);
    split1(v.z, h[2], l[2]); split1(v.w, h[3], l[3]);
    hi = make_uint2((uint32_t)h[0] | ((uint32_t)h[1] << 16),
                    (uint32_t)h[2] | ((uint32_t)h[3] << 16));
    lo = make_uint2((uint32_t)l[0] | ((uint32_t)l[1] << 16),
                    (uint32_t)l[2] | ((uint32_t)l[3] << 16));
}
__device__ __forceinline__ void cp_commit() {
    asm volatile("cp.async.commit_group;" ::: "memory");
}
__device__ __forceinline__ void cp_wait_all() {
    asm volatile("cp.async.wait_all;" ::: "memory");
}
__device__ __forceinline__ void cp16(uint32_t daddr, const void* src) {
    asm volatile("cp.async.cg.shared.global [%0], [%1], 16;"
                 :: "r"(daddr), "l"(src));
}
__device__ __forceinline__ void cp16z(uint32_t daddr, const void* src, int sz) {
    asm volatile("cp.async.cg.shared.global [%0], [%1], 16, %2;"
                 :: "r"(daddr), "l"(src), "r"(sz));
}
// sum 8 packed bf16 (hi image + lo image words) into per-group accumulators
__device__ __forceinline__ void acc_bf16x2(uint32_t w, float* d0, float* d1) {
    *d0 += __bfloat162float(__ushort_as_bfloat16((unsigned short)(w & 0xffff)));
    *d1 += __bfloat162float(__ushort_as_bfloat16((unsigned short)(w >> 16)));
}

// ---------------- Kernel 0: parallel W -> split-bf16 padded images -----------
__global__ __launch_bounds__(256) void wprep_kernel(
    const float* __restrict__ wq, const float* __restrict__ wk,
    const float* __restrict__ wv)
{
    const int mat = blockIdx.x, seg = blockIdx.y;
    const float* w = (mat == 0) ? wq : (mat == 1) ? wk : wv;
    const int t = threadIdx.x;
    int n  = seg * 8 + (t >> 5);
    int k4 = t & 31;
    float4 v = *(const float4*)(w + n * 128 + k4 * 4);
    uint2 hi, lo; split4(v, hi, lo);
    uint32_t off = (uint32_t)(n * WLDH_ + k4 * 4);
    *(uint2*)&g_w16[mat][0][off] = hi;
    *(uint2*)&g_w16[mat][1][off] = lo;
}

// ---------------- Kernel 1: QKV projection (proven MMA core), bf16 epilogue --
#define PALD_ 72
#define PSA_HI_ 0
#define PSA_LO_ (PSA_HI_ + 128 * PALD_ * 2)    // 18432
#define PWA_    (PSA_LO_ + 128 * PALD_ * 2)    // 36864
#define WIMG_   (128 * WLDH_ * 2)              // 34816
#define WPAIR_  (2 * WIMG_)                    // 69632
#define PSM_BYTES_ (PWA_ + WPAIR_)             // 106496 -> 2 CTAs/SM

__global__ void __launch_bounds__(256, 2) proj_mma_kernel(const float* __restrict__ x)
{
    extern __shared__ char sm[];
    const uint32_t smb = smem_u32(sm);
    const int t = threadIdx.x;
    const int pxbase = blockIdx.x * 64;
    const int b = blockIdx.y;

    // prologue: W0 image copy (overlapped by X conversion)
    {
        const char* src = (const char*)g_w16[0];
        uint32_t dst = smb + PWA_;
#pragma unroll
        for (int i = 0; i < 17; i++) {
            int idx = t + i * 256;
            if (idx < WPAIR_ / 16) cp16(dst + idx * 16, src + idx * 16);
        }
        cp_commit();
    }

    // X tile: [128ch][64px] -> split bf16 [ch][px]
#pragma unroll
    for (int j = 0; j < 8; j++) {
        int idx = t + j * 256;
        int c  = idx >> 4;
        int p4 = idx & 15;
        float4 v = *(const float4*)(x + ((size_t)(b * C_ + c)) * HW_ + pxbase + p4 * 4);
        uint2 hi, lo; split4(v, hi, lo);
        uint32_t off = (uint32_t)(c * PALD_ + p4 * 4) * 2;
        *(uint2*)(sm + PSA_HI_ + off) = hi;
        *(uint2*)(sm + PSA_LO_ + off) = lo;
    }

    const int w = t >> 5, lane = t & 31;
    const int m0 = (w & 1) * 32;
    const int n0 = (w >> 1) * 32;
    const int lq = lane & 15;

    const uint32_t a_base = smb + PSA_HI_ +
        (uint32_t)(((lane & 7) + ((lane >> 4) & 1) * 8) * PALD_ +
                   (m0 + ((lane >> 3) & 1) * 8)) * 2;
    const uint32_t b_base = smb + PWA_ +
        (uint32_t)((n0 + (lq & 7)) * WLDH_) * 2 + ((lq >> 3) & 1) * 16;

#pragma unroll 1
    for (int mat = 0; mat < 3; mat++) {
        cp_wait_all();
        __syncthreads();

        float acc[2][4][4];
#pragma unroll
        for (int mt = 0; mt < 2; mt++)
#pragma unroll
            for (int nt = 0; nt < 4; nt++)
#pragma unroll
                for (int e = 0; e < 4; e++) acc[mt][nt][e] = 0.f;

#pragma unroll
        for (int ks = 0; ks < 8; ks++) {
            uint32_t ahi[2][4], alo[2][4];
#pragma unroll
            for (int mt = 0; mt < 2; mt++) {
                uint32_t aa = a_base + (uint32_t)(ks * 16 * PALD_ * 2 + mt * 32);
                ldsm_x4_trans(ahi[mt], aa);
                ldsm_x4_trans(alo[mt], aa + (PSA_LO_ - PSA_HI_));
            }
#pragma unroll
            for (int nt = 0; nt < 4; nt++) {
                uint32_t ba = b_base + (uint32_t)(nt * 8 * WLDH_ * 2 + ks * 32);
                uint32_t bh0, bh1, bl0, bl1;
                ldsm_x2(bh0, bh1, ba);
                ldsm_x2(bl0, bl1, ba + WIMG_);
#pragma unroll
                for (int mt = 0; mt < 2; mt++) {
                    mma16816(acc[mt][nt], ahi[mt], bh0, bh1);
                    mma16816(acc[mt][nt], ahi[mt], bl0, bl1);
                    mma16816(acc[mt][nt], alo[mt], bh0, bh1);
                }
            }
        }

        // epilogue: pixel-major split-bf16 images for all 3 mats
        {
            unsigned short* ih = (mat == 0) ? g_qh : (mat == 1) ? g_kh : g_vh;
            unsigned short* il = (mat == 0) ? g_ql : (mat == 1) ? g_kl : g_vl;
#pragma unroll
            for (int mt = 0; mt < 2; mt++) {
#pragma unroll
                for (int nt = 0; nt < 4; nt++) {
                    int nn = n0 + nt * 8 + (lane & 3) * 2;       // even ch
                    int f0 = pxbase + m0 + mt * 16 + (lane >> 2);
                    int f1 = f0 + 8;
                    unsigned short h0,l0,h1,l1,h2,l2,h3,l3;
                    split1(acc[mt][nt][0], h0, l0);
                    split1(acc[mt][nt][1], h1, l1);
                    split1(acc[mt][nt][2], h2, l2);
                    split1(acc[mt][nt][3], h3, l3);
                    size_t p0 = ((size_t)(b * HW_) + f0) * C_ + nn;
                    size_t p1 = ((size_t)(b * HW_) + f1) * C_ + nn;
                    *(ushort2*)&ih[p0] = make_ushort2(h0, h1);
                    *(ushort2*)&il[p0] = make_ushort2(l0, l1);
                    *(ushort2*)&ih[p1] = make_ushort2(h2, h3);
                    *(ushort2*)&il[p1] = make_ushort2(l2, l3);
                }
            }
        }
        __syncthreads();

        if (mat < 2) {
            const char* src = (const char*)g_w16[mat + 1];
            uint32_t dst = smb + PWA_;
#pragma unroll
            for (int i = 0; i < 17; i++) {
                int idx = t + i * 256;
                if (idx < WPAIR_ / 16) cp16(dst + idx * 16, src + idx * 16);
            }
            cp_commit();
        }
    }
}

// ---------------- Kernel 2: HMMA windowed attention --------------------------
// 8x8 px tiles, grid (8,8,4), 256 threads = 8 warps.
#define NBR_ 196
#define NBK_ 208
#define LP_  208            // logits pitch (floats)
#define WP_  216            // weights pitch (halfs); 432 B rows
#define QLD_ 136            // Q pitch in halfs (272 B; 272%128==16 -> conflict-free)
// SMEM map (bytes)
#define SQ_HI2_ 0
#define SQIMG2_ (64 * QLD_ * 2)              // 17408
#define SQ_LO2_ SQIMG2_
#define SB2_    (2 * SQIMG2_)                // 34816
#define SBIMG2_ (NBK_ * 72 * 2)              // 29952
#define SBHALF2_ (2 * SBIMG2_)               // 59904
#define SC2_    (SB2_ + 2 * SBHALF2_)        // 154624
#define SWH2_   SC2_
#define SWL2_   (SC2_ + 64 * WP_ * 2)        // +27648
#define SREL2_  (SC2_ + 56320)               // 210944
#define ASM_BYTES_ (SREL2_ + 448)            // 211392

__global__ void __launch_bounds__(256, 1) attn_kernel(
    const float* __restrict__ relx, const float* __restrict__ rely,
    float* __restrict__ out)
{
    extern __shared__ char sm[];
    const uint32_t smb = smem_u32(sm);
    const int t = threadIdx.x;
    const int w = t >> 5, lane = t & 31;
    const int lq = lane & 15;
    const int b  = blockIdx.z;
    const int x0 = blockIdx.x * 8, y0 = blockIdx.y * 8;
    float* srel = (float*)(sm + SREL2_);

    if (t < 112) srel[t] = (t < 56) ? relx[t] : rely[t - 56];

    // ---- load Q tile [px 64][ch 128] hi/lo; rows contiguous 256 B ----
#pragma unroll
    for (int img = 0; img < 2; img++) {
        const unsigned short* src = img ? g_ql : g_qh;
        uint32_t dbase = smb + (img ? SQ_LO2_ : SQ_HI2_);
#pragma unroll
        for (int i0 = 0; i0 < 4; i0++) {
            int i = t + i0 * 256;            // 1024 = 64 px x 16 chunks
            int px = i >> 4, c8 = i & 15;
            size_t g = ((size_t)(b * HW_) + (size_t)(y0 + (px >> 3)) * W_ + x0 + (px & 7)) * C_;
            cp16(dbase + (uint32_t)(px * (QLD_ * 2) + c8 * 16), src + g + c8 * 8);
        }
    }
    // ---- load K: 208 nbr rows x 128 ch, 2 ch-halves; halo zero-fill ----
#pragma unroll
    for (int half = 0; half < 2; half++) {
#pragma unroll
        for (int img = 0; img < 2; img++) {
            const unsigned short* src0 = img ? g_kl : g_kh;
            uint32_t dbase = smb + SB2_ + half * SBHALF2_ + img * SBIMG2_;
            for (int i = t; i < NBK_ * 8; i += 256) {
                int r = i >> 3, c8 = i & 7;
                int yy = r / 14, xx = r - yy * 14;
                int gy = y0 - PAD_ + yy, gx = x0 - PAD_ + xx;
                bool inb = (r < NBR_) && ((unsigned)gy < H_) && ((unsigned)gx < W_);
                const unsigned short* s = src0 +
                    ((size_t)(b * HW_ + (inb ? gy : 0) * W_ + (inb ? gx : 0))) * C_ +
                    half * 64 + c8 * 8;
                cp16z(dbase + (uint32_t)(r * 144 + c8 * 16), s, inb ? 16 : 0);
            }
        }
    }
    cp_commit();
    cp_wait_all();
    __syncthreads();

    // ---- QK MMA: warp -> m-tile (w&3), n-tiles [(w>>2)*13, +13) ----
    const int mq = (w & 3) * 16;
    const int nbase = (w >> 2) * 13;
    // A operand (non-trans): row = px, col = ch
    const uint32_t aq_base = smb + SQ_HI2_ +
        (uint32_t)((mq + (lane & 15)) * (QLD_ * 2)) + (uint32_t)((lane >> 4) * 16);
    const uint32_t bK_off = (uint32_t)((lq & 7) * 144 + ((lq >> 3) & 1) * 16);

    float acc[13][4];
#pragma unroll
    for (int j = 0; j < 13; j++)
#pragma unroll
        for (int e = 0; e < 4; e++) acc[j][e] = 0.f;

#pragma unroll
    for (int half = 0; half < 2; half++) {
        const uint32_t kbase = smb + SB2_ + half * SBHALF2_;
#pragma unroll
        for (int ks = 0; ks < 4; ks++) {
            int ch0 = half * 64 + ks * 16;
            uint32_t aa = aq_base + (uint32_t)(ch0 * 2);
            uint32_t ahi[4], alo[4];
            ldsm_x4(ahi, aa);
            ldsm_x4(alo, aa + SQIMG2_);
#pragma unroll
            for (int j = 0; j < 13; j++) {
                uint32_t ba = kbase + bK_off + (uint32_t)((nbase + j) * 8 * 144 + ks * 32);
                uint32_t bh0, bh1, bl0, bl1;
                ldsm_x2(bh0, bh1, ba);
                ldsm_x2(bl0, bl1, ba + SBIMG2_);
                mma16816(acc[j], ahi, bh0, bh1);
                mma16816(acc[j], ahi, bl0, bl1);
                mma16816(acc[j], alo, bh0, bh1);
            }
        }
    }

    // ---- store logits [64][208] ----
    {
        float* lg = (float*)(sm + SC2_);
        int r0 = mq + (lane >> 2);
#pragma unroll
        for (int j = 0; j < 13; j++) {
            int col = (nbase + j) * 8 + (lane & 3) * 2;
            *(float2*)&lg[(size_t)r0 * LP_ + col]       = make_float2(acc[j][0], acc[j][1]);
            *(float2*)&lg[(size_t)(r0 + 8) * LP_ + col] = make_float2(acc[j][2], acc[j][3]);
        }
    }
    __syncthreads();

    // ---- issue V loads into the K region (overlaps softmax) ----
#pragma unroll
    for (int half = 0; half < 2; half++) {
#pragma unroll
        for (int img = 0; img < 2; img++) {
            const unsigned short* src0 = img ? g_vl : g_vh;
            uint32_t dbase = smb + SB2_ + half * SBHALF2_ + img * SBIMG2_;
            for (int i = t; i < NBK_ * 8; i += 256) {
                int r = i >> 3, c8 = i & 7;
                int yy = r / 14, xx = r - yy * 14;
                int gy = y0 - PAD_ + yy, gx = x0 - PAD_ + xx;
                bool inb = (r < NBR_) && ((unsigned)gy < H_) && ((unsigned)gx < W_);
                const unsigned short* s = src0 +
                    ((size_t)(b * HW_ + (inb ? gy : 0) * W_ + (inb ? gx : 0))) * C_ +
                    half * 64 + c8 * 8;
                cp16z(dbase + (uint32_t)(r * 144 + c8 * 16), s, inb ? 16 : 0);
            }
        }
    }
    cp_commit();

    // ---- softmax + bias (threads 0..63, one pixel each) ----
    float w49[49];
    if (t < 64) {
        const int p = t, ty = p >> 3, tx = p & 7;
        const float* lg = (const float*)(sm + SC2_);
#pragma unroll
        for (int ki = 0; ki < 7; ki++)
#pragma unroll
            for (int kj = 0; kj < 7; kj++)
                w49[ki * 7 + kj] = lg[(size_t)p * LP_ + (ty + ki) * 14 + tx + kj];

        // q channel-group sums: vectorized uint4 reads of the Q row
        float qs[16];
#pragma unroll
        for (int i = 0; i < 16; i++) qs[i] = 0.f;
#pragma unroll
        for (int c8 = 0; c8 < 16; c8++) {
            uint32_t off = (uint32_t)(p * (QLD_ * 2) + c8 * 16);
            uint4 hv = *(const uint4*)(sm + SQ_HI2_ + off);
            uint4 lv = *(const uint4*)(sm + SQ_LO2_ + off);
            float* d = (c8 & 1) ? qs + 8 : qs;
            acc_bf16x2(hv.x, d + 0, d + 1); acc_bf16x2(lv.x, d + 0, d + 1);
            acc_bf16x2(hv.y, d + 2, d + 3); acc_bf16x2(lv.y, d + 2, d + 3);
            acc_bf16x2(hv.z, d + 4, d + 5); acc_bf16x2(lv.z, d + 4, d + 5);
            acc_bf16x2(hv.w, d + 6, d + 7); acc_bf16x2(lv.w, d + 6, d + 7);
        }
        float bx[7], by[7];
#pragma unroll
        for (int kj = 0; kj < 7; kj++) {
            float s = 0.f;
#pragma unroll
            for (int xi = 0; xi < 8; xi++) s = fmaf(qs[xi], srel[xi * 7 + kj], s);
            bx[kj] = s;
        }
#pragma unroll
        for (int ki = 0; ki < 7; ki++) {
            float s = 0.f;
#pragma unroll
            for (int yi = 0; yi < 8; yi++) s = fmaf(qs[8 + yi], srel[56 + yi * 7 + ki], s);
            by[ki] = s;
        }
        float m = -1e30f;
#pragma unroll
        for (int ki = 0; ki < 7; ki++)
#pragma unroll
            for (int kj = 0; kj < 7; kj++) {
                float v = w49[ki * 7 + kj] + bx[kj] + by[ki];
                w49[ki * 7 + kj] = v;
                m = fmaxf(m, v);
            }
        float ssum = 0.f;
#pragma unroll
        for (int i = 0; i < 49; i++) { float e = __expf(w49[i] - m); w49[i] = e; ssum += e; }
        float inv = 1.f / ssum;
#pragma unroll
        for (int i = 0; i < 49; i++) w49[i] *= inv;
    }
    __syncthreads();

    // ---- write weights matrix [px 64][216] hi/lo (zero + scatter) ----
    if (t < 64) {
        const int p = t, ty = p >> 3, tx = p & 7;
#pragma unroll
        for (int i = 0; i < 27; i++) {
            *(uint4*)(sm + SWH2_ + p * 432 + i * 16) = make_uint4(0, 0, 0, 0);
            *(uint4*)(sm + SWL2_ + p * 432 + i * 16) = make_uint4(0, 0, 0, 0);
        }
#pragma unroll
        for (int ki = 0; ki < 7; ki++)
#pragma unroll
            for (int kj = 0; kj < 7; kj++) {
                int nbr = (ty + ki) * 14 + tx + kj;
                unsigned short h, l;
                split1(w49[ki * 7 + kj], h, l);
                *(unsigned short*)(sm + SWH2_ + p * 432 + nbr * 2) = h;
                *(unsigned short*)(sm + SWL2_ + p * 432 + nbr * 2) = l;
            }
    }
    cp_wait_all();
    __syncthreads();

    // ---- AV MMA (transposed): out_t[ch,px]; warp -> ch m-tile w ----
    {
        const int half = w >> 2;
        const int mch  = (w & 3) * 16;
        const uint32_t av_base = smb + SB2_ + half * SBHALF2_ +
            (uint32_t)(((lane & 7) + ((lane >> 4) & 1) * 8) * 144 +
                       (mch + ((lane >> 3) & 1) * 8) * 2);
        const uint32_t bw_off = (uint32_t)((lq & 7) * 432 + ((lq >> 3) & 1) * 16);

        float oacc[8][4];
#pragma unroll
        for (int j = 0; j < 8; j++)
#pragma unroll
            for (int e = 0; e < 4; e++) oacc[j][e] = 0.f;

#pragma unroll
        for (int ks = 0; ks < 13; ks++) {
            uint32_t aa = av_base + (uint32_t)(ks * 16 * 144);
            uint32_t vhi[4], vlo[4];
            ldsm_x4_trans(vhi, aa);
            ldsm_x4_trans(vlo, aa + SBIMG2_);
#pragma unroll
            for (int j = 0; j < 8; j++) {
                uint32_t ba = smb + SWH2_ + bw_off + (uint32_t)(j * 8 * 432 + ks * 32);
                uint32_t wh0, wh1, wl0, wl1;
                ldsm_x2(wh0, wh1, ba);
                ldsm_x2(wl0, wl1, ba + (SWL2_ - SWH2_));
                mma16816(oacc[j], vhi, wh0, wh1);
                mma16816(oacc[j], vhi, wl0, wl1);
                mma16816(oacc[j], vlo, wh0, wh1);
            }
        }

        int ch0 = w * 16 + (lane >> 2);
#pragma unroll
        for (int j = 0; j < 8; j++) {
            int y = y0 + j;
            int xx = x0 + (lane & 3) * 2;
            size_t o0 = ((size_t)(b * C_ + ch0) * H_ + y) * W_ + xx;
            size_t o1 = ((size_t)(b * C_ + ch0 + 8) * H_ + y) * W_ + xx;
            *(float2*)&out[o0] = make_float2(oacc[j][0], oacc[j][1]);
            *(float2*)&out[o1] = make_float2(oacc[j][2], oacc[j][3]);
        }
    }
}

// ---------------- launch -----------------------------------------------------
extern "C" void kernel_launch(void* const* d_in, const int* in_sizes, int n_in,
                              void* d_out, int out_size)
{
    const float* x    = (const float*)d_in[0];
    const float* wq   = (const float*)d_in[1];
    const float* wk   = (const float*)d_in[2];
    const float* wv   = (const float*)d_in[3];
    const float* relx = (const float*)d_in[4];
    const float* rely = (const float*)d_in[5];
    float* out = (float*)d_out;

    cudaFuncSetAttribute(proj_mma_kernel,
                         cudaFuncAttributeMaxDynamicSharedMemorySize, PSM_BYTES_);
    cudaFuncSetAttribute(attn_kernel,
                         cudaFuncAttributeMaxDynamicSharedMemorySize, ASM_BYTES_);

    wprep_kernel<<<dim3(3, 16), 256>>>(wq, wk, wv);
    proj_mma_kernel<<<dim3(64, B_), 256, PSM_BYTES_>>>(x);
    attn_kernel<<<dim3(W_ / 8, H_ / 8, B_), 256, ASM_BYTES_>>>(relx, rely, out);
}